// round 13
// baseline (speedup 1.0000x reference)
#include <cuda_runtime.h>
#include <cuda_bf16.h>

#define NCAP 100000
typedef unsigned long long u64;
typedef unsigned int u32;

__device__ float g_pre_a[(size_t)NCAP * 128];
__device__ float g_pre_b[(size_t)NCAP * 128];
__device__ float g_deg[NCAP];

// ---------------- fp32x2 helpers (node_post) ----------------
__device__ __forceinline__ u64 pack2(float lo, float hi) {
    u64 r; asm("mov.b64 %0,{%1,%2};" : "=l"(r) : "f"(lo), "f"(hi)); return r;
}
__device__ __forceinline__ float2 unpack2(u64 v) {
    float2 f; asm("mov.b64 {%0,%1},%2;" : "=f"(f.x), "=f"(f.y) : "l"(v)); return f;
}
__device__ __forceinline__ u64 ffma2(u64 a, u64 b, u64 c) {
    u64 d; asm("fma.rn.f32x2 %0,%1,%2,%3;" : "=l"(d) : "l"(a), "l"(b), "l"(c)); return d;
}
// shifted softplus, base-2 form
__device__ __forceinline__ float sspf(float x) {
    float t = fabsf(x) * -1.4426950408889634f;
    float u; asm("ex2.approx.f32 %0, %1;" : "=f"(u) : "f"(t));
    float v = fmaf(0.5f, u, 0.5f);
    float w; asm("lg2.approx.f32 %0, %1;" : "=f"(w) : "f"(v));
    return fmaf(0.6931471805599453f, w, fmaxf(x, 0.0f));
}

// ---------------- mma.sync helpers (sm_80+ baseline) ----------------
__device__ __forceinline__ u32 smem_u32(const void* p) {
    u32 a;
    asm("{ .reg .u64 t; cvta.to.shared.u64 t, %1; cvt.u32.u64 %0, t; }" : "=r"(a) : "l"(p));
    return a;
}
__device__ __forceinline__ void ldmx4(u32 addr, u32& r0, u32& r1, u32& r2, u32& r3) {
    asm volatile("ldmatrix.sync.aligned.m8n8.x4.shared.b16 {%0,%1,%2,%3}, [%4];"
                 : "=r"(r0), "=r"(r1), "=r"(r2), "=r"(r3) : "r"(addr));
}
__device__ __forceinline__ void mma16816(float c[4], const u32 a[4], u32 b0, u32 b1) {
    asm volatile(
        "mma.sync.aligned.m16n8k16.row.col.f32.bf16.bf16.f32 "
        "{%0,%1,%2,%3},{%4,%5,%6,%7},{%8,%9},{%0,%1,%2,%3};"
        : "+f"(c[0]), "+f"(c[1]), "+f"(c[2]), "+f"(c[3])
        : "r"(a[0]), "r"(a[1]), "r"(a[2]), "r"(a[3]), "r"(b0), "r"(b1));
}
__device__ __forceinline__ void red_v2(float* p, float x, float y) {
    asm volatile("red.global.add.v2.f32 [%0], {%1, %2};" :: "l"(p), "f"(x), "f"(y) : "memory");
}
__device__ __forceinline__ void split2(float v0, float v1, u32& hi, u32& lo) {
    __nv_bfloat162 h = __floats2bfloat162_rn(v0, v1);
    float l0 = v0 - __low2float(h), l1 = v1 - __high2float(h);
    __nv_bfloat162 lw = __floats2bfloat162_rn(l0, l1);
    hi = *(u32*)&h; lo = *(u32*)&lw;
}

// ---------------- edge kernel: HMMA bf16, 12 warps, shared scratch ----------
#define TPB 384
#define NW  12
#define SB_STRIP 0        // 12 warps x 32 ints         1536
#define SB_B1    1536     // 128 f32                     512
#define SB_B2    2048     // 64 f32                      256
#define SB_PB1   2304     // 64 f32                      256
#define SB_W1H   2560     // [128 j][144B]              18432
#define SB_W1L   20992
#define SB_W2H   39424    // [64 j][272B]               17408
#define SB_W2L   56832
#define SB_P1H   74240    // [64 j][144B]                9216
#define SB_P1L   83456
#define SB_SCR   92672    // 12 x 8704
#define SMEM_BYTES 197120

__global__ void __launch_bounds__(TPB, 1)
edge_kernel(const float* __restrict__ edge_feats,
            const int* __restrict__ srcp, const int* __restrict__ dstp,
            const float* __restrict__ eu_w1, const float* __restrict__ eu_b1,
            const float* __restrict__ eu_w2, const float* __restrict__ eu_b2,
            const float* __restrict__ pe_w1, const float* __restrict__ pe_b1,
            float* __restrict__ agg, float* __restrict__ out_edge,
            int E, int numWT) {
    extern __shared__ char smem[];
    float* sB1f  = (float*)(smem + SB_B1);
    float* sB2f  = (float*)(smem + SB_B2);
    float* sPb1f = (float*)(smem + SB_PB1);

    const int tid = threadIdx.x;
    const int w = tid >> 5, L = tid & 31;
    const int gid = L >> 2, tig = L & 3;

    for (int i = tid; i < 128 * 64; i += TPB) {   // W1c: j=0..127, k=0..63
        int j = i >> 6, k = i & 63;
        float wv = eu_w1[(128 + k) * 128 + j];
        __nv_bfloat16 h = __float2bfloat16(wv);
        float lo = wv - __bfloat162float(h);
        *(__nv_bfloat16*)(smem + SB_W1H + j * 144 + k * 2) = h;
        *(__nv_bfloat16*)(smem + SB_W1L + j * 144 + k * 2) = __float2bfloat16(lo);
    }
    for (int i = tid; i < 64 * 128; i += TPB) {   // W2
        int k = i >> 6, j = i & 63;
        float wv = eu_w2[i];
        __nv_bfloat16 h = __float2bfloat16(wv);
        float lo = wv - __bfloat162float(h);
        *(__nv_bfloat16*)(smem + SB_W2H + j * 272 + k * 2) = h;
        *(__nv_bfloat16*)(smem + SB_W2L + j * 272 + k * 2) = __float2bfloat16(lo);
    }
    for (int i = tid; i < 64 * 64; i += TPB) {    // Pe1
        int k = i >> 6, j = i & 63;
        float wv = pe_w1[i];
        __nv_bfloat16 h = __float2bfloat16(wv);
        float lo = wv - __bfloat162float(h);
        *(__nv_bfloat16*)(smem + SB_P1H + j * 144 + k * 2) = h;
        *(__nv_bfloat16*)(smem + SB_P1L + j * 144 + k * 2) = __float2bfloat16(lo);
    }
    if (tid < 128) sB1f[tid] = eu_b1[tid];
    if (tid < 64) { sB2f[tid] = eu_b2[tid]; sPb1f[tid] = pe_b1[tid]; }
    __syncthreads();

    const u32 smb = smem_u32(smem);
    int* strip = (int*)(smem + SB_STRIP) + w * 32;
    char* scr = smem + SB_SCR + w * 8704;
    const u32 SCRw = smb + SB_SCR + (u32)w * 8704;
    const u32 a_lane144 = (u32)(L & 15) * 144 + ((u32)(L >> 4) << 4);
    const u32 a_lane272 = (u32)(L & 15) * 272 + ((u32)(L >> 4) << 4);
    const u32 b_lane144 = (u32)(L & 7) * 144 + ((u32)(L >> 3) << 4);
    const u32 b_lane272 = (u32)(L & 7) * 272 + ((u32)(L >> 3) << 4);

    for (int wt = blockIdx.x * NW + w; wt < numWT; wt += gridDim.x * NW) {
        const int base = wt * 16;
        {
            int v = 0;
            if (L < 16) { int g = base + L;      if (g < E) v = srcp[g]; }
            else        { int g = base + L - 16; if (g < E) v = dstp[g]; }
            strip[L] = v;
            int row = L >> 1, half = L & 1;
            bool ok = (base + row) < E;
            const float4* gp = (const float4*)(edge_feats + (size_t)(base + row) * 64 + half * 32);
            u32 hi[16], lo[16];
#pragma unroll
            for (int q = 0; q < 8; q++) {
                float4 v4 = ok ? gp[q] : make_float4(0.f, 0.f, 0.f, 0.f);
                split2(v4.x, v4.y, hi[2 * q], lo[2 * q]);
                split2(v4.z, v4.w, hi[2 * q + 1], lo[2 * q + 1]);
            }
            char* ph = scr + row * 144 + half * 64;
            char* pl = ph + 2304;
#pragma unroll
            for (int q = 0; q < 4; q++) {
                *(uint4*)(ph + q * 16) = make_uint4(hi[4 * q], hi[4 * q + 1], hi[4 * q + 2], hi[4 * q + 3]);
                *(uint4*)(pl + q * 16) = make_uint4(lo[4 * q], lo[4 * q + 1], lo[4 * q + 2], lo[4 * q + 3]);
            }
        }
        __syncwarp();

        u32 aH[4][4], aL[4][4];
#pragma unroll
        for (int ks = 0; ks < 4; ks++) {
            ldmx4(SCRw + a_lane144 + ks * 32,        aH[ks][0], aH[ks][1], aH[ks][2], aH[ks][3]);
            ldmx4(SCRw + 2304 + a_lane144 + ks * 32, aL[ks][0], aL[ks][1], aL[ks][2], aL[ks][3]);
        }
        __syncwarp();

        const int s0 = strip[gid],     d0 = strip[16 + gid];
        const int s1 = strip[gid + 8], d1 = strip[24 + gid];
        const float* pA0 = g_pre_a + (size_t)s0 * 128;
        const float* pB0 = g_pre_b + (size_t)d0 * 128;
        const float* pA1 = g_pre_a + (size_t)s1 * 128;
        const float* pB1 = g_pre_b + (size_t)d1 * 128;

        // ---- L1 (gathers software-pipelined one nt ahead) ----
        {
            int col0 = 2 * tig;
            float2 pa0 = *(const float2*)(pA0 + col0);
            float2 pb0 = *(const float2*)(pB0 + col0);
            float2 pa1 = *(const float2*)(pA1 + col0);
            float2 pb1v = *(const float2*)(pB1 + col0);
#pragma unroll
            for (int nt = 0; nt < 16; nt++) {
                int col = 8 * nt + 2 * tig;
                int ncol = (nt < 15) ? col + 8 : col;
                // issue NEXT iteration's gathers before this iteration's mma burst
                float2 qa0 = *(const float2*)(pA0 + ncol);
                float2 qb0 = *(const float2*)(pB0 + ncol);
                float2 qa1 = *(const float2*)(pA1 + ncol);
                float2 qb1 = *(const float2*)(pB1 + ncol);

                u32 bh[8], bl[8];
                u32 wbH = smb + SB_W1H + (u32)nt * 8 * 144 + b_lane144;
                u32 wbL = smb + SB_W1L + (u32)nt * 8 * 144 + b_lane144;
                ldmx4(wbH,      bh[0], bh[1], bh[2], bh[3]);
                ldmx4(wbH + 64, bh[4], bh[5], bh[6], bh[7]);
                ldmx4(wbL,      bl[0], bl[1], bl[2], bl[3]);
                ldmx4(wbL + 64, bl[4], bl[5], bl[6], bl[7]);
                float c[4] = {0.f, 0.f, 0.f, 0.f};
#pragma unroll
                for (int ks = 0; ks < 4; ks++) {
                    mma16816(c, aH[ks], bh[2 * ks], bh[2 * ks + 1]);
                    mma16816(c, aL[ks], bh[2 * ks], bh[2 * ks + 1]);
                    mma16816(c, aH[ks], bl[2 * ks], bl[2 * ks + 1]);
                }
                float2 bb = *(float2*)(sB1f + col);
                float v00 = sspf(c[0] + pa0.x + pb0.x + bb.x);
                float v01 = sspf(c[1] + pa0.y + pb0.y + bb.y);
                float v10 = sspf(c[2] + pa1.x + pb1v.x + bb.x);
                float v11 = sspf(c[3] + pa1.y + pb1v.y + bb.y);
                u32 h0, l0, h1, l1;
                split2(v00, v01, h0, l0);
                split2(v10, v11, h1, l1);
                u32 o0 = (u32)gid * 272 + (u32)col * 2;
                u32 o1 = (u32)(gid + 8) * 272 + (u32)col * 2;
                *(u32*)(scr + o0) = h0;
                *(u32*)(scr + 4352 + o0) = l0;
                *(u32*)(scr + o1) = h1;
                *(u32*)(scr + 4352 + o1) = l1;
                pa0 = qa0; pb0 = qb0; pa1 = qa1; pb1v = qb1;
            }
        }
        __syncwarp();

        u32 a2H[8][4], a2L[8][4];
#pragma unroll
        for (int ks = 0; ks < 8; ks++) {
            ldmx4(SCRw + a_lane272 + ks * 32,        a2H[ks][0], a2H[ks][1], a2H[ks][2], a2H[ks][3]);
            ldmx4(SCRw + 4352 + a_lane272 + ks * 32, a2L[ks][0], a2L[ks][1], a2L[ks][2], a2L[ks][3]);
        }
        __syncwarp();

        // ---- L2 ----
#pragma unroll
        for (int nt = 0; nt < 8; nt++) {
            u32 bh[16], bl[16];
            u32 wbH = smb + SB_W2H + (u32)nt * 8 * 272 + b_lane272;
            u32 wbL = smb + SB_W2L + (u32)nt * 8 * 272 + b_lane272;
#pragma unroll
            for (int kp = 0; kp < 4; kp++) {
                ldmx4(wbH + kp * 64, bh[4 * kp], bh[4 * kp + 1], bh[4 * kp + 2], bh[4 * kp + 3]);
                ldmx4(wbL + kp * 64, bl[4 * kp], bl[4 * kp + 1], bl[4 * kp + 2], bl[4 * kp + 3]);
            }
            float c[4] = {0.f, 0.f, 0.f, 0.f};
#pragma unroll
            for (int ks = 0; ks < 8; ks++) {
                mma16816(c, a2H[ks], bh[2 * ks], bh[2 * ks + 1]);
                mma16816(c, a2L[ks], bh[2 * ks], bh[2 * ks + 1]);
                mma16816(c, a2H[ks], bl[2 * ks], bl[2 * ks + 1]);
            }
            int col = 8 * nt + 2 * tig;
            float2 bb = *(float2*)(sB2f + col);
            float v00 = c[0] + bb.x, v01 = c[1] + bb.y;
            float v10 = c[2] + bb.x, v11 = c[3] + bb.y;
            if (base + gid < E)
                *(float2*)(out_edge + (size_t)(base + gid) * 64 + col) = make_float2(v00, v01);
            if (base + gid + 8 < E)
                *(float2*)(out_edge + (size_t)(base + gid + 8) * 64 + col) = make_float2(v10, v11);
            u32 h0, l0, h1, l1;
            split2(v00, v01, h0, l0);
            split2(v10, v11, h1, l1);
            u32 o0 = (u32)gid * 144 + (u32)col * 2;
            u32 o1 = (u32)(gid + 8) * 144 + (u32)col * 2;
            *(u32*)(scr + o0) = h0;
            *(u32*)(scr + 2304 + o0) = l0;
            *(u32*)(scr + o1) = h1;
            *(u32*)(scr + 2304 + o1) = l1;
        }
        __syncwarp();

        u32 a3H[4][4], a3L[4][4];
#pragma unroll
        for (int ks = 0; ks < 4; ks++) {
            ldmx4(SCRw + a_lane144 + ks * 32,        a3H[ks][0], a3H[ks][1], a3H[ks][2], a3H[ks][3]);
            ldmx4(SCRw + 2304 + a_lane144 + ks * 32, a3L[ks][0], a3L[ks][1], a3L[ks][2], a3L[ks][3]);
        }

        // ---- L3 ----
#pragma unroll
        for (int nt = 0; nt < 8; nt++) {
            u32 bh[8], bl[8];
            u32 wbH = smb + SB_P1H + (u32)nt * 8 * 144 + b_lane144;
            u32 wbL = smb + SB_P1L + (u32)nt * 8 * 144 + b_lane144;
            ldmx4(wbH,      bh[0], bh[1], bh[2], bh[3]);
            ldmx4(wbH + 64, bh[4], bh[5], bh[6], bh[7]);
            ldmx4(wbL,      bl[0], bl[1], bl[2], bl[3]);
            ldmx4(wbL + 64, bl[4], bl[5], bl[6], bl[7]);
            float c[4] = {0.f, 0.f, 0.f, 0.f};
#pragma unroll
            for (int ks = 0; ks < 4; ks++) {
                mma16816(c, a3H[ks], bh[2 * ks], bh[2 * ks + 1]);
                mma16816(c, a3L[ks], bh[2 * ks], bh[2 * ks + 1]);
                mma16816(c, a3H[ks], bl[2 * ks], bl[2 * ks + 1]);
            }
            int col = 8 * nt + 2 * tig;
            float2 bb = *(float2*)(sPb1f + col);
            if (base + gid < E)
                red_v2(agg + (size_t)d0 * 64 + col,
                       sspf(c[0] + bb.x), sspf(c[1] + bb.y));
            if (base + gid + 8 < E)
                red_v2(agg + (size_t)d1 * 64 + col,
                       sspf(c[2] + bb.x), sspf(c[3] + bb.y));
        }
        if (L >= 16 && base + (L - 16) < E) atomicAdd(g_deg + strip[L], 1.0f);
        __syncwarp();
    }
}

// ---------------- node precompute: HMMA bf16 3-term; grid.y selects half ----
// pre_a[n] = nf[n] @ eu_w1[0:64]; pre_b[n] = nf[n] @ eu_w1[64:128]
#define NPRE_W1H 0        // [128 j][144B] 18432
#define NPRE_W1L 18432
#define NPRE_SCR 36864    // 12 x 4608
#define NPRE_SMEM 92160

__global__ void __launch_bounds__(TPB, 1)
node_pre_kernel(const float* __restrict__ node_feats,
                const float* __restrict__ eu_w1, int N, int numNT) {
    extern __shared__ char smem[];
    const int tid = threadIdx.x;
    const int w = tid >> 5, L = tid & 31;
    const int gid = L >> 2, tig = L & 3;
    const int half = blockIdx.y;

    for (int i = tid; i < 128 * 64; i += TPB) {
        int j = i >> 6, k = i & 63;
        float wv = eu_w1[(half * 64 + k) * 128 + j];
        __nv_bfloat16 h = __float2bfloat16(wv);
        float lo = wv - __bfloat162float(h);
        *(__nv_bfloat16*)(smem + NPRE_W1H + j * 144 + k * 2) = h;
        *(__nv_bfloat16*)(smem + NPRE_W1L + j * 144 + k * 2) = __float2bfloat16(lo);
    }
    __syncthreads();

    const u32 smb = smem_u32(smem);
    char* scr = smem + NPRE_SCR + w * 4608;
    const u32 SCRw = smb + NPRE_SCR + (u32)w * 4608;
    const u32 a_lane144 = (u32)(L & 15) * 144 + ((u32)(L >> 4) << 4);
    const u32 b_lane144 = (u32)(L & 7) * 144 + ((u32)(L >> 3) << 4);
    float* outp = half ? g_pre_b : g_pre_a;

    for (int nt_tile = blockIdx.x * NW + w; nt_tile < numNT; nt_tile += gridDim.x * NW) {
        const int base = nt_tile * 16;
        {
            int row = L >> 1, hf = L & 1;
            bool ok = (base + row) < N;
            const float4* gp = (const float4*)(node_feats + (size_t)(base + row) * 64 + hf * 32);
            u32 hi[16], lo[16];
#pragma unroll
            for (int q = 0; q < 8; q++) {
                float4 v4 = ok ? gp[q] : make_float4(0.f, 0.f, 0.f, 0.f);
                split2(v4.x, v4.y, hi[2 * q], lo[2 * q]);
                split2(v4.z, v4.w, hi[2 * q + 1], lo[2 * q + 1]);
            }
            char* ph = scr + row * 144 + hf * 64;
            char* pl = ph + 2304;
#pragma unroll
            for (int q = 0; q < 4; q++) {
                *(uint4*)(ph + q * 16) = make_uint4(hi[4 * q], hi[4 * q + 1], hi[4 * q + 2], hi[4 * q + 3]);
                *(uint4*)(pl + q * 16) = make_uint4(lo[4 * q], lo[4 * q + 1], lo[4 * q + 2], lo[4 * q + 3]);
            }
        }
        __syncwarp();

        u32 aH[4][4], aL[4][4];
#pragma unroll
        for (int ks = 0; ks < 4; ks++) {
            ldmx4(SCRw + a_lane144 + ks * 32,        aH[ks][0], aH[ks][1], aH[ks][2], aH[ks][3]);
            ldmx4(SCRw + 2304 + a_lane144 + ks * 32, aL[ks][0], aL[ks][1], aL[ks][2], aL[ks][3]);
        }

        const bool ok0 = (base + gid) < N, ok1 = (base + gid + 8) < N;
#pragma unroll
        for (int nt = 0; nt < 16; nt++) {
            u32 bh[8], bl[8];
            u32 wbH = smb + NPRE_W1H + (u32)nt * 8 * 144 + b_lane144;
            u32 wbL = wbH + 18432;
            ldmx4(wbH,      bh[0], bh[1], bh[2], bh[3]);
            ldmx4(wbH + 64, bh[4], bh[5], bh[6], bh[7]);
            ldmx4(wbL,      bl[0], bl[1], bl[2], bl[3]);
            ldmx4(wbL + 64, bl[4], bl[5], bl[6], bl[7]);
            float c[4] = {0.f, 0.f, 0.f, 0.f};
#pragma unroll
            for (int ks = 0; ks < 4; ks++) {
                mma16816(c, aH[ks], bh[2 * ks], bh[2 * ks + 1]);
                mma16816(c, aL[ks], bh[2 * ks], bh[2 * ks + 1]);
                mma16816(c, aH[ks], bl[2 * ks], bl[2 * ks + 1]);
            }
            int col = 8 * nt + 2 * tig;
            if (ok0)
                *(float2*)(outp + (size_t)(base + gid) * 128 + col) = make_float2(c[0], c[1]);
            if (ok1)
                *(float2*)(outp + (size_t)(base + gid + 8) * 128 + col) = make_float2(c[2], c[3]);
        }
        __syncwarp();
    }
}

// ---------------- node post (unchanged: deferred pe_w2 + 2-layer) ----------
#define P68 68
#define NP_PE2T 0
#define NP_W1T  4352
#define NP_W2T  8704
#define NP_PB2  13056
#define NP_B1   13120
#define NP_B2   13184
#define NP_DEG  13248
#define NP_A    13376
#define NP_X2   22080
#define NP_FLOATS 30784

__global__ void __launch_bounds__(512, 1)
node_post_kernel(const float* __restrict__ node_feats,
                 const float* __restrict__ pe_w2, const float* __restrict__ pe_b2,
                 const float* __restrict__ w1, const float* __restrict__ b1,
                 const float* __restrict__ w2, const float* __restrict__ b2,
                 float* __restrict__ node_out, int N) {
    extern __shared__ float sm[];
    float* sPe2T = sm + NP_PE2T;
    float* sW1T  = sm + NP_W1T;
    float* sW2T  = sm + NP_W2T;
    float* sPb2  = sm + NP_PB2;
    float* sB1   = sm + NP_B1;
    float* sB2   = sm + NP_B2;
    float* sDeg  = sm + NP_DEG;
    float* sA    = sm + NP_A;
    float* sX2   = sm + NP_X2;
    float* sT    = sA;

    const int tid = threadIdx.x;
    for (int i = tid; i < 4096; i += 512) {
        int k = i >> 6, j = i & 63;
        sPe2T[j * P68 + k] = pe_w2[i];
        sW1T[j * P68 + k]  = w1[i];
        sW2T[j * P68 + k]  = w2[i];
    }
    if (tid < 64) { sPb2[tid] = pe_b2[tid]; sB1[tid] = b1[tid]; sB2[tid] = b2[tid]; }
    const int base = blockIdx.x * 128;
    if (tid < 128) {
        int g = base + tid;
        sDeg[tid] = (g < N) ? g_deg[g] : 0.0f;
    }
    {
        const float4* g4 = (const float4*)(node_out) + (size_t)base * 16;
#pragma unroll
        for (int i = tid; i < 2048; i += 512) {
            float4 v = make_float4(0.f, 0.f, 0.f, 0.f);
            if (base + (i >> 4) < N) v = g4[i];
            int row = i >> 4, c = i & 15;
            *(float4*)(sA + row * P68 + c * 4) = v;
        }
    }
    __syncthreads();
    const int w = tid >> 5, L = tid & 31;
    const int n0 = w * 8;

    {
        u64 a0[8][2];
#pragma unroll
        for (int e = 0; e < 8; e++) { a0[e][0] = 0; a0[e][1] = 0; }
        const float* wr0 = sPe2T + L * P68;
        const float* wr1 = wr0 + 32 * P68;
#pragma unroll 4
        for (int k0 = 0; k0 < 64; k0 += 4) {
            ulonglong2 wj0 = *(const ulonglong2*)(wr0 + k0);
            ulonglong2 wj1 = *(const ulonglong2*)(wr1 + k0);
#pragma unroll
            for (int e = 0; e < 8; e++) {
                ulonglong2 xu = *(const ulonglong2*)(sA + (n0 + e) * P68 + k0);
                a0[e][0] = ffma2(xu.x, wj0.x, a0[e][0]);
                a0[e][0] = ffma2(xu.y, wj0.y, a0[e][0]);
                a0[e][1] = ffma2(xu.x, wj1.x, a0[e][1]);
                a0[e][1] = ffma2(xu.y, wj1.y, a0[e][1]);
            }
        }
        float c0 = sPb2[L], c1 = sPb2[L + 32];
        float xr[8][2];
#pragma unroll
        for (int e = 0; e < 8; e++) {
            float dg = sDeg[n0 + e];
            float2 p0 = unpack2(a0[e][0]), p1 = unpack2(a0[e][1]);
            xr[e][0] = p0.x + p0.y + dg * c0;
            xr[e][1] = p1.x + p1.y + dg * c1;
        }
        __syncwarp();
#pragma unroll
        for (int e = 0; e < 8; e++) {
            sX2[(n0 + e) * P68 + L]      = xr[e][0];
            sX2[(n0 + e) * P68 + L + 32] = xr[e][1];
        }
    }
    __syncwarp();
    {
        u64 a1[8][2];
#pragma unroll
        for (int e = 0; e < 8; e++) { a1[e][0] = 0; a1[e][1] = 0; }
        const float* wr0 = sW1T + L * P68;
        const float* wr1 = wr0 + 32 * P68;
#pragma unroll 4
        for (int k0 = 0; k0 < 64; k0 += 4) {
            ulonglong2 wj0 = *(const ulonglong2*)(wr0 + k0);
            ulonglong2 wj1 = *(const ulonglong2*)(wr1 + k0);
#pragma unroll
            for (int e = 0; e < 8; e++) {
                ulonglong2 xu = *(const ulonglong2*)(sX2 + (n0 + e) * P68 + k0);
                a1[e][0] = ffma2(xu.x, wj0.x, a1[e][0]);
                a1[e][0] = ffma2(xu.y, wj0.y, a1[e][0]);
                a1[e][1] = ffma2(xu.x, wj1.x, a1[e][1]);
                a1[e][1] = ffma2(xu.y, wj1.y, a1[e][1]);
            }
        }
        float c0 = sB1[L], c1 = sB1[L + 32];
#pragma unroll
        for (int e = 0; e < 8; e++) {
            float2 p0 = unpack2(a1[e][0]), p1 = unpack2(a1[e][1]);
            sT[(n0 + e) * P68 + L]      = sspf(p0.x + p0.y + c0);
            sT[(n0 + e) * P68 + L + 32] = sspf(p1.x + p1.y + c1);
        }
    }
    __syncwarp();
    {
        u64 a2[8][2];
#pragma unroll
        for (int e = 0; e < 8; e++) { a2[e][0] = 0; a2[e][1] = 0; }
        const float* wr0 = sW2T + L * P68;
        const float* wr1 = wr0 + 32 * P68;
#pragma unroll 4
        for (int k0 = 0; k0 < 64; k0 += 4) {
            ulonglong2 wj0 = *(const ulonglong2*)(wr0 + k0);
            ulonglong2 wj1 = *(const ulonglong2*)(wr1 + k0);
#pragma unroll
            for (int e = 0; e < 8; e++) {
                ulonglong2 xu = *(const ulonglong2*)(sT + (n0 + e) * P68 + k0);
                a2[e][0] = ffma2(xu.x, wj0.x, a2[e][0]);
                a2[e][0] = ffma2(xu.y, wj0.y, a2[e][0]);
                a2[e][1] = ffma2(xu.x, wj1.x, a2[e][1]);
                a2[e][1] = ffma2(xu.y, wj1.y, a2[e][1]);
            }
        }
        float c0 = sB2[L], c1 = sB2[L + 32];
#pragma unroll
        for (int e = 0; e < 8; e++) {
            int g = base + n0 + e;
            if (g < N) {
                float nf0 = node_feats[(size_t)g * 64 + L];
                float nf1 = node_feats[(size_t)g * 64 + L + 32];
                float2 p0 = unpack2(a2[e][0]), p1 = unpack2(a2[e][1]);
                node_out[(size_t)g * 64 + L]      = p0.x + p0.y + c0 + nf0;
                node_out[(size_t)g * 64 + L + 32] = p1.x + p1.y + c1 + nf1;
            }
        }
    }
}

extern "C" void kernel_launch(void* const* d_in, const int* in_sizes, int n_in,
                              void* d_out, int out_size) {
    const float* node_feats = (const float*)d_in[0];
    const float* edge_feats = (const float*)d_in[1];
    const int*   src  = (const int*)d_in[2];
    const int*   dst  = (const int*)d_in[3];
    const float* eu_w1 = (const float*)d_in[4];
    const float* eu_b1 = (const float*)d_in[5];
    const float* eu_w2 = (const float*)d_in[6];
    const float* eu_b2 = (const float*)d_in[7];
    const float* pe_w1 = (const float*)d_in[10];
    const float* pe_b1 = (const float*)d_in[11];
    const float* pe_w2 = (const float*)d_in[12];
    const float* pe_b2 = (const float*)d_in[13];
    const float* pn2_w1 = (const float*)d_in[14];
    const float* pn2_b1 = (const float*)d_in[15];
    const float* pn2_w2 = (const float*)d_in[16];
    const float* pn2_b2 = (const float*)d_in[17];

    const int N = in_sizes[0] / 64;
    const int E = in_sizes[1] / 64;
    float* out_node = (float*)d_out;
    float* out_edge = out_node + (size_t)N * 64;

    cudaFuncSetAttribute(edge_kernel, cudaFuncAttributeMaxDynamicSharedMemorySize, SMEM_BYTES);
    cudaFuncSetAttribute(node_pre_kernel, cudaFuncAttributeMaxDynamicSharedMemorySize, NPRE_SMEM);
    cudaFuncSetAttribute(node_post_kernel, cudaFuncAttributeMaxDynamicSharedMemorySize, NP_FLOATS * 4);

    cudaMemsetAsync(out_node, 0, (size_t)N * 64 * sizeof(float));
    void* degp = 0;
    cudaGetSymbolAddress(&degp, g_deg);
    cudaMemsetAsync(degp, 0, (size_t)N * sizeof(float));

    int sms = 0;
    cudaDeviceGetAttribute(&sms, cudaDevAttrMultiProcessorCount, 0);
    if (sms <= 0) sms = 148;

    int numNT = (N + 15) / 16;
    int gx = sms;
    if (gx * NW > numNT) gx = (numNT + NW - 1) / NW;
    if (gx < 1) gx = 1;
    dim3 gpre(gx, 2);
    node_pre_kernel<<<gpre, TPB, NPRE_SMEM>>>(node_feats, eu_w1, N, numNT);

    int numWT = (E + 15) / 16;
    int grid = sms;
    if (grid * NW > numWT) grid = (numWT + NW - 1) / NW;
    if (grid < 1) grid = 1;
    edge_kernel<<<grid, TPB, SMEM_BYTES>>>(
        edge_feats, src, dst, eu_w1, eu_b1, eu_w2, eu_b2,
        pe_w1, pe_b1, out_node, out_edge, E, numWT);

    node_post_kernel<<<(N + 127) / 128, 512, NP_FLOATS * 4>>>(
        node_feats, pe_w2, pe_b2, pn2_w1, pn2_b1, pn2_w2, pn2_b2, out_node, N);
}

// round 14
// speedup vs baseline: 1.0719x; 1.0719x over previous
#include <cuda_runtime.h>
#include <cuda_bf16.h>

#define NCAP 100000
typedef unsigned long long u64;
typedef unsigned int u32;

__device__ float g_pre_a[(size_t)NCAP * 128];
__device__ float g_pre_b[(size_t)NCAP * 128];
__device__ float g_deg[NCAP];

// shifted softplus, base-2 form
__device__ __forceinline__ float sspf(float x) {
    float t = fabsf(x) * -1.4426950408889634f;
    float u; asm("ex2.approx.f32 %0, %1;" : "=f"(u) : "f"(t));
    float v = fmaf(0.5f, u, 0.5f);
    float w; asm("lg2.approx.f32 %0, %1;" : "=f"(w) : "f"(v));
    return fmaf(0.6931471805599453f, w, fmaxf(x, 0.0f));
}

// ---------------- mma.sync helpers (sm_80+ baseline) ----------------
__device__ __forceinline__ u32 smem_u32(const void* p) {
    u32 a;
    asm("{ .reg .u64 t; cvta.to.shared.u64 t, %1; cvt.u32.u64 %0, t; }" : "=r"(a) : "l"(p));
    return a;
}
__device__ __forceinline__ void ldmx4(u32 addr, u32& r0, u32& r1, u32& r2, u32& r3) {
    asm volatile("ldmatrix.sync.aligned.m8n8.x4.shared.b16 {%0,%1,%2,%3}, [%4];"
                 : "=r"(r0), "=r"(r1), "=r"(r2), "=r"(r3) : "r"(addr));
}
__device__ __forceinline__ void mma16816(float c[4], const u32 a[4], u32 b0, u32 b1) {
    asm volatile(
        "mma.sync.aligned.m16n8k16.row.col.f32.bf16.bf16.f32 "
        "{%0,%1,%2,%3},{%4,%5,%6,%7},{%8,%9},{%0,%1,%2,%3};"
        : "+f"(c[0]), "+f"(c[1]), "+f"(c[2]), "+f"(c[3])
        : "r"(a[0]), "r"(a[1]), "r"(a[2]), "r"(a[3]), "r"(b0), "r"(b1));
}
__device__ __forceinline__ void red_v2(float* p, float x, float y) {
    asm volatile("red.global.add.v2.f32 [%0], {%1, %2};" :: "l"(p), "f"(x), "f"(y) : "memory");
}
__device__ __forceinline__ void split2(float v0, float v1, u32& hi, u32& lo) {
    __nv_bfloat162 h = __floats2bfloat162_rn(v0, v1);
    float l0 = v0 - __low2float(h), l1 = v1 - __high2float(h);
    __nv_bfloat162 lw = __floats2bfloat162_rn(l0, l1);
    hi = *(u32*)&h; lo = *(u32*)&lw;
}

// ---------------- edge kernel: HMMA bf16, 12 warps, shared scratch ----------
#define TPB 384
#define NW  12
#define SB_STRIP 0        // 12 warps x 32 ints         1536
#define SB_B1    1536     // 128 f32                     512
#define SB_B2    2048     // 64 f32                      256
#define SB_PB1   2304     // 64 f32                      256
#define SB_W1H   2560     // [128 j][144B]              18432
#define SB_W1L   20992
#define SB_W2H   39424    // [64 j][272B]               17408
#define SB_W2L   56832
#define SB_P1H   74240    // [64 j][144B]                9216
#define SB_P1L   83456
#define SB_SCR   92672    // 12 x 8704
#define SMEM_BYTES 197120

__global__ void __launch_bounds__(TPB, 1)
edge_kernel(const float* __restrict__ edge_feats,
            const int* __restrict__ srcp, const int* __restrict__ dstp,
            const float* __restrict__ eu_w1, const float* __restrict__ eu_b1,
            const float* __restrict__ eu_w2, const float* __restrict__ eu_b2,
            const float* __restrict__ pe_w1, const float* __restrict__ pe_b1,
            float* __restrict__ agg, float* __restrict__ out_edge,
            int E, int numWT) {
    extern __shared__ char smem[];
    float* sB1f  = (float*)(smem + SB_B1);
    float* sB2f  = (float*)(smem + SB_B2);
    float* sPb1f = (float*)(smem + SB_PB1);

    const int tid = threadIdx.x;
    const int w = tid >> 5, L = tid & 31;
    const int gid = L >> 2, tig = L & 3;

    for (int i = tid; i < 128 * 64; i += TPB) {   // W1c: j=0..127, k=0..63
        int j = i >> 6, k = i & 63;
        float wv = eu_w1[(128 + k) * 128 + j];
        __nv_bfloat16 h = __float2bfloat16(wv);
        float lo = wv - __bfloat162float(h);
        *(__nv_bfloat16*)(smem + SB_W1H + j * 144 + k * 2) = h;
        *(__nv_bfloat16*)(smem + SB_W1L + j * 144 + k * 2) = __float2bfloat16(lo);
    }
    for (int i = tid; i < 64 * 128; i += TPB) {   // W2
        int k = i >> 6, j = i & 63;
        float wv = eu_w2[i];
        __nv_bfloat16 h = __float2bfloat16(wv);
        float lo = wv - __bfloat162float(h);
        *(__nv_bfloat16*)(smem + SB_W2H + j * 272 + k * 2) = h;
        *(__nv_bfloat16*)(smem + SB_W2L + j * 272 + k * 2) = __float2bfloat16(lo);
    }
    for (int i = tid; i < 64 * 64; i += TPB) {    // Pe1
        int k = i >> 6, j = i & 63;
        float wv = pe_w1[i];
        __nv_bfloat16 h = __float2bfloat16(wv);
        float lo = wv - __bfloat162float(h);
        *(__nv_bfloat16*)(smem + SB_P1H + j * 144 + k * 2) = h;
        *(__nv_bfloat16*)(smem + SB_P1L + j * 144 + k * 2) = __float2bfloat16(lo);
    }
    if (tid < 128) sB1f[tid] = eu_b1[tid];
    if (tid < 64) { sB2f[tid] = eu_b2[tid]; sPb1f[tid] = pe_b1[tid]; }
    __syncthreads();

    const u32 smb = smem_u32(smem);
    int* strip = (int*)(smem + SB_STRIP) + w * 32;
    char* scr = smem + SB_SCR + w * 8704;
    const u32 SCRw = smb + SB_SCR + (u32)w * 8704;
    const u32 a_lane144 = (u32)(L & 15) * 144 + ((u32)(L >> 4) << 4);
    const u32 a_lane272 = (u32)(L & 15) * 272 + ((u32)(L >> 4) << 4);
    const u32 b_lane144 = (u32)(L & 7) * 144 + ((u32)(L >> 3) << 4);
    const u32 b_lane272 = (u32)(L & 7) * 272 + ((u32)(L >> 3) << 4);

    for (int wt = blockIdx.x * NW + w; wt < numWT; wt += gridDim.x * NW) {
        const int base = wt * 16;
        {
            int v = 0;
            if (L < 16) { int g = base + L;      if (g < E) v = srcp[g]; }
            else        { int g = base + L - 16; if (g < E) v = dstp[g]; }
            strip[L] = v;
            int row = L >> 1, half = L & 1;
            bool ok = (base + row) < E;
            const float4* gp = (const float4*)(edge_feats + (size_t)(base + row) * 64 + half * 32);
            u32 hi[16], lo[16];
#pragma unroll
            for (int q = 0; q < 8; q++) {
                float4 v4 = ok ? gp[q] : make_float4(0.f, 0.f, 0.f, 0.f);
                split2(v4.x, v4.y, hi[2 * q], lo[2 * q]);
                split2(v4.z, v4.w, hi[2 * q + 1], lo[2 * q + 1]);
            }
            char* ph = scr + row * 144 + half * 64;
            char* pl = ph + 2304;
#pragma unroll
            for (int q = 0; q < 4; q++) {
                *(uint4*)(ph + q * 16) = make_uint4(hi[4 * q], hi[4 * q + 1], hi[4 * q + 2], hi[4 * q + 3]);
                *(uint4*)(pl + q * 16) = make_uint4(lo[4 * q], lo[4 * q + 1], lo[4 * q + 2], lo[4 * q + 3]);
            }
        }
        __syncwarp();

        u32 aH[4][4], aL[4][4];
#pragma unroll
        for (int ks = 0; ks < 4; ks++) {
            ldmx4(SCRw + a_lane144 + ks * 32,        aH[ks][0], aH[ks][1], aH[ks][2], aH[ks][3]);
            ldmx4(SCRw + 2304 + a_lane144 + ks * 32, aL[ks][0], aL[ks][1], aL[ks][2], aL[ks][3]);
        }
        __syncwarp();

        const int s0 = strip[gid],     d0 = strip[16 + gid];
        const int s1 = strip[gid + 8], d1 = strip[24 + gid];

        // ---- L1 ----
#pragma unroll
        for (int nt = 0; nt < 16; nt++) {
            u32 bh[8], bl[8];
            u32 wbH = smb + SB_W1H + (u32)nt * 8 * 144 + b_lane144;
            u32 wbL = smb + SB_W1L + (u32)nt * 8 * 144 + b_lane144;
            ldmx4(wbH,      bh[0], bh[1], bh[2], bh[3]);
            ldmx4(wbH + 64, bh[4], bh[5], bh[6], bh[7]);
            ldmx4(wbL,      bl[0], bl[1], bl[2], bl[3]);
            ldmx4(wbL + 64, bl[4], bl[5], bl[6], bl[7]);
            float c[4] = {0.f, 0.f, 0.f, 0.f};
#pragma unroll
            for (int ks = 0; ks < 4; ks++) {
                mma16816(c, aH[ks], bh[2 * ks], bh[2 * ks + 1]);
                mma16816(c, aL[ks], bh[2 * ks], bh[2 * ks + 1]);
                mma16816(c, aH[ks], bl[2 * ks], bl[2 * ks + 1]);
            }
            int col = 8 * nt + 2 * tig;
            float2 bb = *(float2*)(sB1f + col);
            float2 pa0 = *(const float2*)(g_pre_a + (size_t)s0 * 128 + col);
            float2 pb0 = *(const float2*)(g_pre_b + (size_t)d0 * 128 + col);
            float2 pa1 = *(const float2*)(g_pre_a + (size_t)s1 * 128 + col);
            float2 pb1v = *(const float2*)(g_pre_b + (size_t)d1 * 128 + col);
            float v00 = sspf(c[0] + pa0.x + pb0.x + bb.x);
            float v01 = sspf(c[1] + pa0.y + pb0.y + bb.y);
            float v10 = sspf(c[2] + pa1.x + pb1v.x + bb.x);
            float v11 = sspf(c[3] + pa1.y + pb1v.y + bb.y);
            u32 h0, l0, h1, l1;
            split2(v00, v01, h0, l0);
            split2(v10, v11, h1, l1);
            u32 o0 = (u32)gid * 272 + (u32)col * 2;
            u32 o1 = (u32)(gid + 8) * 272 + (u32)col * 2;
            *(u32*)(scr + o0) = h0;
            *(u32*)(scr + 4352 + o0) = l0;
            *(u32*)(scr + o1) = h1;
            *(u32*)(scr + 4352 + o1) = l1;
        }
        __syncwarp();

        u32 a2H[8][4], a2L[8][4];
#pragma unroll
        for (int ks = 0; ks < 8; ks++) {
            ldmx4(SCRw + a_lane272 + ks * 32,        a2H[ks][0], a2H[ks][1], a2H[ks][2], a2H[ks][3]);
            ldmx4(SCRw + 4352 + a_lane272 + ks * 32, a2L[ks][0], a2L[ks][1], a2L[ks][2], a2L[ks][3]);
        }
        __syncwarp();

        // ---- L2 ----
#pragma unroll
        for (int nt = 0; nt < 8; nt++) {
            u32 bh[16], bl[16];
            u32 wbH = smb + SB_W2H + (u32)nt * 8 * 272 + b_lane272;
            u32 wbL = smb + SB_W2L + (u32)nt * 8 * 272 + b_lane272;
#pragma unroll
            for (int kp = 0; kp < 4; kp++) {
                ldmx4(wbH + kp * 64, bh[4 * kp], bh[4 * kp + 1], bh[4 * kp + 2], bh[4 * kp + 3]);
                ldmx4(wbL + kp * 64, bl[4 * kp], bl[4 * kp + 1], bl[4 * kp + 2], bl[4 * kp + 3]);
            }
            float c[4] = {0.f, 0.f, 0.f, 0.f};
#pragma unroll
            for (int ks = 0; ks < 8; ks++) {
                mma16816(c, a2H[ks], bh[2 * ks], bh[2 * ks + 1]);
                mma16816(c, a2L[ks], bh[2 * ks], bh[2 * ks + 1]);
                mma16816(c, a2H[ks], bl[2 * ks], bl[2 * ks + 1]);
            }
            int col = 8 * nt + 2 * tig;
            float2 bb = *(float2*)(sB2f + col);
            float v00 = c[0] + bb.x, v01 = c[1] + bb.y;
            float v10 = c[2] + bb.x, v11 = c[3] + bb.y;
            if (base + gid < E)
                *(float2*)(out_edge + (size_t)(base + gid) * 64 + col) = make_float2(v00, v01);
            if (base + gid + 8 < E)
                *(float2*)(out_edge + (size_t)(base + gid + 8) * 64 + col) = make_float2(v10, v11);
            u32 h0, l0, h1, l1;
            split2(v00, v01, h0, l0);
            split2(v10, v11, h1, l1);
            u32 o0 = (u32)gid * 144 + (u32)col * 2;
            u32 o1 = (u32)(gid + 8) * 144 + (u32)col * 2;
            *(u32*)(scr + o0) = h0;
            *(u32*)(scr + 2304 + o0) = l0;
            *(u32*)(scr + o1) = h1;
            *(u32*)(scr + 2304 + o1) = l1;
        }
        __syncwarp();

        u32 a3H[4][4], a3L[4][4];
#pragma unroll
        for (int ks = 0; ks < 4; ks++) {
            ldmx4(SCRw + a_lane144 + ks * 32,        a3H[ks][0], a3H[ks][1], a3H[ks][2], a3H[ks][3]);
            ldmx4(SCRw + 2304 + a_lane144 + ks * 32, a3L[ks][0], a3L[ks][1], a3L[ks][2], a3L[ks][3]);
        }

        // ---- L3 ----
#pragma unroll
        for (int nt = 0; nt < 8; nt++) {
            u32 bh[8], bl[8];
            u32 wbH = smb + SB_P1H + (u32)nt * 8 * 144 + b_lane144;
            u32 wbL = smb + SB_P1L + (u32)nt * 8 * 144 + b_lane144;
            ldmx4(wbH,      bh[0], bh[1], bh[2], bh[3]);
            ldmx4(wbH + 64, bh[4], bh[5], bh[6], bh[7]);
            ldmx4(wbL,      bl[0], bl[1], bl[2], bl[3]);
            ldmx4(wbL + 64, bl[4], bl[5], bl[6], bl[7]);
            float c[4] = {0.f, 0.f, 0.f, 0.f};
#pragma unroll
            for (int ks = 0; ks < 4; ks++) {
                mma16816(c, a3H[ks], bh[2 * ks], bh[2 * ks + 1]);
                mma16816(c, a3L[ks], bh[2 * ks], bh[2 * ks + 1]);
                mma16816(c, a3H[ks], bl[2 * ks], bl[2 * ks + 1]);
            }
            int col = 8 * nt + 2 * tig;
            float2 bb = *(float2*)(sPb1f + col);
            if (base + gid < E)
                red_v2(agg + (size_t)d0 * 64 + col,
                       sspf(c[0] + bb.x), sspf(c[1] + bb.y));
            if (base + gid + 8 < E)
                red_v2(agg + (size_t)d1 * 64 + col,
                       sspf(c[2] + bb.x), sspf(c[3] + bb.y));
        }
        if (L >= 16 && base + (L - 16) < E) atomicAdd(g_deg + strip[L], 1.0f);
        __syncwarp();
    }
}

// ---------------- node precompute: HMMA bf16 3-term, 16-node warp tiles ----
#define NP_W1AH 0        // [128 j][144B] 18432
#define NP_W1AL 18432
#define NP_W1BH 36864
#define NP_W1BL 55296
#define NP_SCRB 73728    // 12 x 4608
#define NPRE_SMEM 129024

__global__ void __launch_bounds__(TPB, 1)
node_pre_kernel(const float* __restrict__ node_feats,
                const float* __restrict__ eu_w1, int N, int numNT) {
    extern __shared__ char smem[];
    const int tid = threadIdx.x;
    const int w = tid >> 5, L = tid & 31;
    const int gid = L >> 2, tig = L & 3;

    for (int i = tid; i < 128 * 64; i += TPB) {
        int j = i >> 6, k = i & 63;
        float wa = eu_w1[k * 128 + j];
        float wb = eu_w1[(64 + k) * 128 + j];
        __nv_bfloat16 ha = __float2bfloat16(wa);
        __nv_bfloat16 hb = __float2bfloat16(wb);
        float la = wa - __bfloat162float(ha);
        float lb = wb - __bfloat162float(hb);
        *(__nv_bfloat16*)(smem + NP_W1AH + j * 144 + k * 2) = ha;
        *(__nv_bfloat16*)(smem + NP_W1AL + j * 144 + k * 2) = __float2bfloat16(la);
        *(__nv_bfloat16*)(smem + NP_W1BH + j * 144 + k * 2) = hb;
        *(__nv_bfloat16*)(smem + NP_W1BL + j * 144 + k * 2) = __float2bfloat16(lb);
    }
    __syncthreads();

    const u32 smb = smem_u32(smem);
    char* scr = smem + NP_SCRB + w * 4608;
    const u32 SCRw = smb + NP_SCRB + (u32)w * 4608;
    const u32 a_lane144 = (u32)(L & 15) * 144 + ((u32)(L >> 4) << 4);
    const u32 b_lane144 = (u32)(L & 7) * 144 + ((u32)(L >> 3) << 4);

    for (int nt_tile = blockIdx.x * NW + w; nt_tile < numNT; nt_tile += gridDim.x * NW) {
        const int base = nt_tile * 16;
        {
            int row = L >> 1, half = L & 1;
            bool ok = (base + row) < N;
            const float4* gp = (const float4*)(node_feats + (size_t)(base + row) * 64 + half * 32);
            u32 hi[16], lo[16];
#pragma unroll
            for (int q = 0; q < 8; q++) {
                float4 v4 = ok ? gp[q] : make_float4(0.f, 0.f, 0.f, 0.f);
                split2(v4.x, v4.y, hi[2 * q], lo[2 * q]);
                split2(v4.z, v4.w, hi[2 * q + 1], lo[2 * q + 1]);
            }
            char* ph = scr + row * 144 + half * 64;
            char* pl = ph + 2304;
#pragma unroll
            for (int q = 0; q < 4; q++) {
                *(uint4*)(ph + q * 16) = make_uint4(hi[4 * q], hi[4 * q + 1], hi[4 * q + 2], hi[4 * q + 3]);
                *(uint4*)(pl + q * 16) = make_uint4(lo[4 * q], lo[4 * q + 1], lo[4 * q + 2], lo[4 * q + 3]);
            }
        }
        __syncwarp();

        u32 aH[4][4], aL[4][4];
#pragma unroll
        for (int ks = 0; ks < 4; ks++) {
            ldmx4(SCRw + a_lane144 + ks * 32,        aH[ks][0], aH[ks][1], aH[ks][2], aH[ks][3]);
            ldmx4(SCRw + 2304 + a_lane144 + ks * 32, aL[ks][0], aL[ks][1], aL[ks][2], aL[ks][3]);
        }

        const bool ok0 = (base + gid) < N, ok1 = (base + gid + 8) < N;
        float* outs[2] = { g_pre_a, g_pre_b };
        const u32 wbase[2] = { NP_W1AH, NP_W1BH };
#pragma unroll
        for (int half = 0; half < 2; half++) {
            float* outp = outs[half];
#pragma unroll
            for (int nt = 0; nt < 16; nt++) {
                u32 bh[8], bl[8];
                u32 wbH = smb + wbase[half] + (u32)nt * 8 * 144 + b_lane144;
                u32 wbL = wbH + 18432;
                ldmx4(wbH,      bh[0], bh[1], bh[2], bh[3]);
                ldmx4(wbH + 64, bh[4], bh[5], bh[6], bh[7]);
                ldmx4(wbL,      bl[0], bl[1], bl[2], bl[3]);
                ldmx4(wbL + 64, bl[4], bl[5], bl[6], bl[7]);
                float c[4] = {0.f, 0.f, 0.f, 0.f};
#pragma unroll
                for (int ks = 0; ks < 4; ks++) {
                    mma16816(c, aH[ks], bh[2 * ks], bh[2 * ks + 1]);
                    mma16816(c, aL[ks], bh[2 * ks], bh[2 * ks + 1]);
                    mma16816(c, aH[ks], bl[2 * ks], bl[2 * ks + 1]);
                }
                int col = 8 * nt + 2 * tig;
                if (ok0)
                    *(float2*)(outp + (size_t)(base + gid) * 128 + col) = make_float2(c[0], c[1]);
                if (ok1)
                    *(float2*)(outp + (size_t)(base + gid + 8) * 128 + col) = make_float2(c[2], c[3]);
            }
        }
        __syncwarp();
    }
}

// ---------------- node post: HMMA bf16 3-term, 16-node warp tiles ----------
//   X = agg @ pe_w2 + deg*pb2 ; T = ssp(X @ pn2_w1 + b1) ; out = nf + T @ pn2_w2 + b2
#define NPO_P2H 0        // [64 j][144B] 9216
#define NPO_P2L 9216
#define NPO_W1H 18432
#define NPO_W1L 27648
#define NPO_W2H 36864
#define NPO_W2L 46080
#define NPO_PB2 55296    // 64 f32
#define NPO_B1  55552
#define NPO_B2  55808
#define NPO_SCR 56064    // 12 x 4608
#define NPO_SMEM 111360

__global__ void __launch_bounds__(TPB, 1)
node_post_kernel(const float* __restrict__ node_feats,
                 const float* __restrict__ pe_w2, const float* __restrict__ pe_b2,
                 const float* __restrict__ w1, const float* __restrict__ b1,
                 const float* __restrict__ w2, const float* __restrict__ b2,
                 float* __restrict__ node_out, int N, int numNT) {
    extern __shared__ char smem[];
    float* sPb2 = (float*)(smem + NPO_PB2);
    float* sB1f = (float*)(smem + NPO_B1);
    float* sB2f = (float*)(smem + NPO_B2);
    const int tid = threadIdx.x;
    const int w = tid >> 5, L = tid & 31;
    const int gid = L >> 2, tig = L & 3;

    for (int i = tid; i < 64 * 64; i += TPB) {
        int k = i >> 6, j = i & 63;
        float wv = pe_w2[i];
        __nv_bfloat16 h = __float2bfloat16(wv);
        *(__nv_bfloat16*)(smem + NPO_P2H + j * 144 + k * 2) = h;
        *(__nv_bfloat16*)(smem + NPO_P2L + j * 144 + k * 2) = __float2bfloat16(wv - __bfloat162float(h));
        wv = w1[i];
        h = __float2bfloat16(wv);
        *(__nv_bfloat16*)(smem + NPO_W1H + j * 144 + k * 2) = h;
        *(__nv_bfloat16*)(smem + NPO_W1L + j * 144 + k * 2) = __float2bfloat16(wv - __bfloat162float(h));
        wv = w2[i];
        h = __float2bfloat16(wv);
        *(__nv_bfloat16*)(smem + NPO_W2H + j * 144 + k * 2) = h;
        *(__nv_bfloat16*)(smem + NPO_W2L + j * 144 + k * 2) = __float2bfloat16(wv - __bfloat162float(h));
    }
    if (tid < 64) { sPb2[tid] = pe_b2[tid]; sB1f[tid] = b1[tid]; sB2f[tid] = b2[tid]; }
    __syncthreads();

    const u32 smb = smem_u32(smem);
    char* scr = smem + NPO_SCR + w * 4608;
    const u32 SCRw = smb + NPO_SCR + (u32)w * 4608;
    const u32 a_lane144 = (u32)(L & 15) * 144 + ((u32)(L >> 4) << 4);
    const u32 b_lane144 = (u32)(L & 7) * 144 + ((u32)(L >> 3) << 4);

    for (int t = blockIdx.x * NW + w; t < numNT; t += gridDim.x * NW) {
        const int base = t * 16;
        // ---- stage A = agg tile (in node_out region), bf16 hi/lo ----
        {
            int row = L >> 1, hf = L & 1;
            bool ok = (base + row) < N;
            const float4* gp = (const float4*)(node_out + (size_t)(base + row) * 64 + hf * 32);
            u32 hi[16], lo[16];
#pragma unroll
            for (int q = 0; q < 8; q++) {
                float4 v4 = ok ? gp[q] : make_float4(0.f, 0.f, 0.f, 0.f);
                split2(v4.x, v4.y, hi[2 * q], lo[2 * q]);
                split2(v4.z, v4.w, hi[2 * q + 1], lo[2 * q + 1]);
            }
            char* ph = scr + row * 144 + hf * 64;
            char* pl = ph + 2304;
#pragma unroll
            for (int q = 0; q < 4; q++) {
                *(uint4*)(ph + q * 16) = make_uint4(hi[4 * q], hi[4 * q + 1], hi[4 * q + 2], hi[4 * q + 3]);
                *(uint4*)(pl + q * 16) = make_uint4(lo[4 * q], lo[4 * q + 1], lo[4 * q + 2], lo[4 * q + 3]);
            }
        }
        __syncwarp();
        u32 aH[4][4], aL[4][4];
#pragma unroll
        for (int ks = 0; ks < 4; ks++) {
            ldmx4(SCRw + a_lane144 + ks * 32,        aH[ks][0], aH[ks][1], aH[ks][2], aH[ks][3]);
            ldmx4(SCRw + 2304 + a_lane144 + ks * 32, aL[ks][0], aL[ks][1], aL[ks][2], aL[ks][3]);
        }
        __syncwarp();

        const bool ok0 = (base + gid) < N, ok1 = (base + gid + 8) < N;
        float dg0 = ok0 ? g_deg[base + gid] : 0.0f;
        float dg1 = ok1 ? g_deg[base + gid + 8] : 0.0f;

        // ---- P1: X = A @ pe_w2 + deg*pb2 -> scratch ----
#pragma unroll
        for (int nt = 0; nt < 8; nt++) {
            u32 bh[8], bl[8];
            u32 wbH = smb + NPO_P2H + (u32)nt * 8 * 144 + b_lane144;
            u32 wbL = smb + NPO_P2L + (u32)nt * 8 * 144 + b_lane144;
            ldmx4(wbH,      bh[0], bh[1], bh[2], bh[3]);
            ldmx4(wbH + 64, bh[4], bh[5], bh[6], bh[7]);
            ldmx4(wbL,      bl[0], bl[1], bl[2], bl[3]);
            ldmx4(wbL + 64, bl[4], bl[5], bl[6], bl[7]);
            float c[4] = {0.f, 0.f, 0.f, 0.f};
#pragma unroll
            for (int ks = 0; ks < 4; ks++) {
                mma16816(c, aH[ks], bh[2 * ks], bh[2 * ks + 1]);
                mma16816(c, aL[ks], bh[2 * ks], bh[2 * ks + 1]);
                mma16816(c, aH[ks], bl[2 * ks], bl[2 * ks + 1]);
            }
            int col = 8 * nt + 2 * tig;
            float2 bb = *(float2*)(sPb2 + col);
            float x00 = c[0] + dg0 * bb.x, x01 = c[1] + dg0 * bb.y;
            float x10 = c[2] + dg1 * bb.x, x11 = c[3] + dg1 * bb.y;
            u32 h0, l0, h1, l1;
            split2(x00, x01, h0, l0);
            split2(x10, x11, h1, l1);
            u32 o0 = (u32)gid * 144 + (u32)col * 2;
            u32 o1 = (u32)(gid + 8) * 144 + (u32)col * 2;
            *(u32*)(scr + o0) = h0;
            *(u32*)(scr + 2304 + o0) = l0;
            *(u32*)(scr + o1) = h1;
            *(u32*)(scr + 2304 + o1) = l1;
        }
        __syncwarp();
        u32 xH[4][4], xL[4][4];
#pragma unroll
        for (int ks = 0; ks < 4; ks++) {
            ldmx4(SCRw + a_lane144 + ks * 32,        xH[ks][0], xH[ks][1], xH[ks][2], xH[ks][3]);
            ldmx4(SCRw + 2304 + a_lane144 + ks * 32, xL[ks][0], xL[ks][1], xL[ks][2], xL[ks][3]);
        }
        __syncwarp();

        // ---- P2: T = ssp(X @ w1 + b1) -> scratch ----
#pragma unroll
        for (int nt = 0; nt < 8; nt++) {
            u32 bh[8], bl[8];
            u32 wbH = smb + NPO_W1H + (u32)nt * 8 * 144 + b_lane144;
            u32 wbL = smb + NPO_W1L + (u32)nt * 8 * 144 + b_lane144;
            ldmx4(wbH,      bh[0], bh[1], bh[2], bh[3]);
            ldmx4(wbH + 64, bh[4], bh[5], bh[6], bh[7]);
            ldmx4(wbL,      bl[0], bl[1], bl[2], bl[3]);
            ldmx4(wbL + 64, bl[4], bl[5], bl[6], bl[7]);
            float c[4] = {0.f, 0.f, 0.f, 0.f};
#pragma unroll
            for (int ks = 0; ks < 4; ks++) {
                mma16816(c, xH[ks], bh[2 * ks], bh[2 * ks + 1]);
                mma16816(c, xL[ks], bh[2 * ks], bh[2 * ks + 1]);
                mma16816(c, xH[ks], bl[2 * ks], bl[2 * ks + 1]);
            }
            int col = 8 * nt + 2 * tig;
            float2 bb = *(float2*)(sB1f + col);
            float t00 = sspf(c[0] + bb.x), t01 = sspf(c[1] + bb.y);
            float t10 = sspf(c[2] + bb.x), t11 = sspf(c[3] + bb.y);
            u32 h0, l0, h1, l1;
            split2(t00, t01, h0, l0);
            split2(t10, t11, h1, l1);
            u32 o0 = (u32)gid * 144 + (u32)col * 2;
            u32 o1 = (u32)(gid + 8) * 144 + (u32)col * 2;
            *(u32*)(scr + o0) = h0;
            *(u32*)(scr + 2304 + o0) = l0;
            *(u32*)(scr + o1) = h1;
            *(u32*)(scr + 2304 + o1) = l1;
        }
        __syncwarp();
        u32 tH[4][4], tL[4][4];
#pragma unroll
        for (int ks = 0; ks < 4; ks++) {
            ldmx4(SCRw + a_lane144 + ks * 32,        tH[ks][0], tH[ks][1], tH[ks][2], tH[ks][3]);
            ldmx4(SCRw + 2304 + a_lane144 + ks * 32, tL[ks][0], tL[ks][1], tL[ks][2], tL[ks][3]);
        }

        // ---- P3: out = nf + T @ w2 + b2 ----
#pragma unroll
        for (int nt = 0; nt < 8; nt++) {
            u32 bh[8], bl[8];
            u32 wbH = smb + NPO_W2H + (u32)nt * 8 * 144 + b_lane144;
            u32 wbL = smb + NPO_W2L + (u32)nt * 8 * 144 + b_lane144;
            ldmx4(wbH,      bh[0], bh[1], bh[2], bh[3]);
            ldmx4(wbH + 64, bh[4], bh[5], bh[6], bh[7]);
            ldmx4(wbL,      bl[0], bl[1], bl[2], bl[3]);
            ldmx4(wbL + 64, bl[4], bl[5], bl[6], bl[7]);
            float c[4] = {0.f, 0.f, 0.f, 0.f};
#pragma unroll
            for (int ks = 0; ks < 4; ks++) {
                mma16816(c, tH[ks], bh[2 * ks], bh[2 * ks + 1]);
                mma16816(c, tL[ks], bh[2 * ks], bh[2 * ks + 1]);
                mma16816(c, tH[ks], bl[2 * ks], bl[2 * ks + 1]);
            }
            int col = 8 * nt + 2 * tig;
            float2 bb = *(float2*)(sB2f + col);
            if (ok0) {
                float2 nf = *(const float2*)(node_feats + (size_t)(base + gid) * 64 + col);
                *(float2*)(node_out + (size_t)(base + gid) * 64 + col) =
                    make_float2(c[0] + bb.x + nf.x, c[1] + bb.y + nf.y);
            }
            if (ok1) {
                float2 nf = *(const float2*)(node_feats + (size_t)(base + gid + 8) * 64 + col);
                *(float2*)(node_out + (size_t)(base + gid + 8) * 64 + col) =
                    make_float2(c[2] + bb.x + nf.x, c[3] + bb.y + nf.y);
            }
        }
        __syncwarp();
    }
}

extern "C" void kernel_launch(void* const* d_in, const int* in_sizes, int n_in,
                              void* d_out, int out_size) {
    const float* node_feats = (const float*)d_in[0];
    const float* edge_feats = (const float*)d_in[1];
    const int*   src  = (const int*)d_in[2];
    const int*   dst  = (const int*)d_in[3];
    const float* eu_w1 = (const float*)d_in[4];
    const float* eu_b1 = (const float*)d_in[5];
    const float* eu_w2 = (const float*)d_in[6];
    const float* eu_b2 = (const float*)d_in[7];
    const float* pe_w1 = (const float*)d_in[10];
    const float* pe_b1 = (const float*)d_in[11];
    const float* pe_w2 = (const float*)d_in[12];
    const float* pe_b2 = (const float*)d_in[13];
    const float* pn2_w1 = (const float*)d_in[14];
    const float* pn2_b1 = (const float*)d_in[15];
    const float* pn2_w2 = (const float*)d_in[16];
    const float* pn2_b2 = (const float*)d_in[17];

    const int N = in_sizes[0] / 64;
    const int E = in_sizes[1] / 64;
    float* out_node = (float*)d_out;
    float* out_edge = out_node + (size_t)N * 64;

    cudaFuncSetAttribute(edge_kernel, cudaFuncAttributeMaxDynamicSharedMemorySize, SMEM_BYTES);
    cudaFuncSetAttribute(node_pre_kernel, cudaFuncAttributeMaxDynamicSharedMemorySize, NPRE_SMEM);
    cudaFuncSetAttribute(node_post_kernel, cudaFuncAttributeMaxDynamicSharedMemorySize, NPO_SMEM);

    cudaMemsetAsync(out_node, 0, (size_t)N * 64 * sizeof(float));
    void* degp = 0;
    cudaGetSymbolAddress(&degp, g_deg);
    cudaMemsetAsync(degp, 0, (size_t)N * sizeof(float));

    int sms = 0;
    cudaDeviceGetAttribute(&sms, cudaDevAttrMultiProcessorCount, 0);
    if (sms <= 0) sms = 148;

    int numNT = (N + 15) / 16;
    int gpre = sms;
    if (gpre * NW > numNT) gpre = (numNT + NW - 1) / NW;
    if (gpre < 1) gpre = 1;
    node_pre_kernel<<<gpre, TPB, NPRE_SMEM>>>(node_feats, eu_w1, N, numNT);

    int numWT = (E + 15) / 16;
    int grid = sms;
    if (grid * NW > numWT) grid = (numWT + NW - 1) / NW;
    if (grid < 1) grid = 1;
    edge_kernel<<<grid, TPB, SMEM_BYTES>>>(
        edge_feats, src, dst, eu_w1, eu_b1, eu_w2, eu_b2,
        pe_w1, pe_b1, out_node, out_edge, E, numWT);

    node_post_kernel<<<gpre, TPB, NPO_SMEM>>>(
        node_feats, pe_w2, pe_b2, pn2_w1, pn2_b1, pn2_w2, pn2_b2,
        out_node, N, numNT);
}

// round 15
// speedup vs baseline: 1.0856x; 1.0128x over previous
#include <cuda_runtime.h>
#include <cuda_bf16.h>

#define NCAP 100000
typedef unsigned long long u64;
typedef unsigned int u32;

__device__ float g_pre_a[(size_t)NCAP * 128];
__device__ float g_pre_b[(size_t)NCAP * 128];
__device__ float g_deg[NCAP];

// shifted softplus, base-2 form
__device__ __forceinline__ float sspf(float x) {
    float t = fabsf(x) * -1.4426950408889634f;
    float u; asm("ex2.approx.f32 %0, %1;" : "=f"(u) : "f"(t));
    float v = fmaf(0.5f, u, 0.5f);
    float w; asm("lg2.approx.f32 %0, %1;" : "=f"(w) : "f"(v));
    return fmaf(0.6931471805599453f, w, fmaxf(x, 0.0f));
}

// ---------------- mma.sync helpers (sm_80+ baseline) ----------------
__device__ __forceinline__ u32 smem_u32(const void* p) {
    u32 a;
    asm("{ .reg .u64 t; cvta.to.shared.u64 t, %1; cvt.u32.u64 %0, t; }" : "=r"(a) : "l"(p));
    return a;
}
__device__ __forceinline__ void ldmx4(u32 addr, u32& r0, u32& r1, u32& r2, u32& r3) {
    asm volatile("ldmatrix.sync.aligned.m8n8.x4.shared.b16 {%0,%1,%2,%3}, [%4];"
                 : "=r"(r0), "=r"(r1), "=r"(r2), "=r"(r3) : "r"(addr));
}
__device__ __forceinline__ void mma16816(float c[4], const u32 a[4], u32 b0, u32 b1) {
    asm volatile(
        "mma.sync.aligned.m16n8k16.row.col.f32.bf16.bf16.f32 "
        "{%0,%1,%2,%3},{%4,%5,%6,%7},{%8,%9},{%0,%1,%2,%3};"
        : "+f"(c[0]), "+f"(c[1]), "+f"(c[2]), "+f"(c[3])
        : "r"(a[0]), "r"(a[1]), "r"(a[2]), "r"(a[3]), "r"(b0), "r"(b1));
}
__device__ __forceinline__ void red_v2(float* p, float x, float y) {
    asm volatile("red.global.add.v2.f32 [%0], {%1, %2};" :: "l"(p), "f"(x), "f"(y) : "memory");
}
__device__ __forceinline__ void split2(float v0, float v1, u32& hi, u32& lo) {
    __nv_bfloat162 h = __floats2bfloat162_rn(v0, v1);
    float l0 = v0 - __low2float(h), l1 = v1 - __high2float(h);
    __nv_bfloat162 lw = __floats2bfloat162_rn(l0, l1);
    hi = *(u32*)&h; lo = *(u32*)&lw;
}

// ---------------- edge kernel: HMMA bf16, 12 warps, pipelined staging ------
#define TPB 384
#define NW  12
#define SB_STRIP 0        // 12 warps x 32 ints         1536
#define SB_B1    1536     // 128 f32                     512
#define SB_B2    2048     // 64 f32                      256
#define SB_PB1   2304     // 64 f32                      256
#define SB_W1H   2560     // [128 j][144B]              18432
#define SB_W1L   20992
#define SB_W2H   39424    // [64 j][272B]               17408
#define SB_W2L   56832
#define SB_P1H   74240    // [64 j][144B]                9216
#define SB_P1L   83456
#define SB_SCR   92672    // 12 x 8704
#define SMEM_BYTES 197120

__global__ void __launch_bounds__(TPB, 1)
edge_kernel(const float* __restrict__ edge_feats,
            const int* __restrict__ srcp, const int* __restrict__ dstp,
            const float* __restrict__ eu_w1, const float* __restrict__ eu_b1,
            const float* __restrict__ eu_w2, const float* __restrict__ eu_b2,
            const float* __restrict__ pe_w1, const float* __restrict__ pe_b1,
            float* __restrict__ agg, float* __restrict__ out_edge,
            int E, int numWT) {
    extern __shared__ char smem[];
    float* sB1f  = (float*)(smem + SB_B1);
    float* sB2f  = (float*)(smem + SB_B2);
    float* sPb1f = (float*)(smem + SB_PB1);

    const int tid = threadIdx.x;
    const int w = tid >> 5, L = tid & 31;
    const int gid = L >> 2, tig = L & 3;

    for (int i = tid; i < 128 * 64; i += TPB) {   // W1c: j=0..127, k=0..63
        int j = i >> 6, k = i & 63;
        float wv = eu_w1[(128 + k) * 128 + j];
        __nv_bfloat16 h = __float2bfloat16(wv);
        float lo = wv - __bfloat162float(h);
        *(__nv_bfloat16*)(smem + SB_W1H + j * 144 + k * 2) = h;
        *(__nv_bfloat16*)(smem + SB_W1L + j * 144 + k * 2) = __float2bfloat16(lo);
    }
    for (int i = tid; i < 64 * 128; i += TPB) {   // W2
        int k = i >> 6, j = i & 63;
        float wv = eu_w2[i];
        __nv_bfloat16 h = __float2bfloat16(wv);
        float lo = wv - __bfloat162float(h);
        *(__nv_bfloat16*)(smem + SB_W2H + j * 272 + k * 2) = h;
        *(__nv_bfloat16*)(smem + SB_W2L + j * 272 + k * 2) = __float2bfloat16(lo);
    }
    for (int i = tid; i < 64 * 64; i += TPB) {    // Pe1
        int k = i >> 6, j = i & 63;
        float wv = pe_w1[i];
        __nv_bfloat16 h = __float2bfloat16(wv);
        float lo = wv - __bfloat162float(h);
        *(__nv_bfloat16*)(smem + SB_P1H + j * 144 + k * 2) = h;
        *(__nv_bfloat16*)(smem + SB_P1L + j * 144 + k * 2) = __float2bfloat16(lo);
    }
    if (tid < 128) sB1f[tid] = eu_b1[tid];
    if (tid < 64) { sB2f[tid] = eu_b2[tid]; sPb1f[tid] = pe_b1[tid]; }
    __syncthreads();

    const u32 smb = smem_u32(smem);
    int* strip = (int*)(smem + SB_STRIP) + w * 32;
    char* scr = smem + SB_SCR + w * 8704;
    const u32 SCRw = smb + SB_SCR + (u32)w * 8704;
    const u32 a_lane144 = (u32)(L & 15) * 144 + ((u32)(L >> 4) << 4);
    const u32 a_lane272 = (u32)(L & 15) * 272 + ((u32)(L >> 4) << 4);
    const u32 b_lane144 = (u32)(L & 7) * 144 + ((u32)(L >> 3) << 4);
    const u32 b_lane272 = (u32)(L & 7) * 272 + ((u32)(L >> 3) << 4);
    const int stride = gridDim.x * NW;
    const int row = L >> 1, half = L & 1;

    int wt = blockIdx.x * NW + w;
    // ---- prologue: stage tile wt (strip + A1 scratch) ----
    {
        int v = 0;
        int b = wt * 16;
        if (L < 16) { int g = b + L;      if (wt < numWT && g < E) v = srcp[g]; }
        else        { int g = b + L - 16; if (wt < numWT && g < E) v = dstp[g]; }
        strip[L] = v;
        bool ok = (wt < numWT) && (b + row) < E;
        const float4* gp = (const float4*)(edge_feats + (size_t)(b + row) * 64 + half * 32);
        u32 hi[16], lo[16];
#pragma unroll
        for (int q = 0; q < 8; q++) {
            float4 v4 = ok ? gp[q] : make_float4(0.f, 0.f, 0.f, 0.f);
            split2(v4.x, v4.y, hi[2 * q], lo[2 * q]);
            split2(v4.z, v4.w, hi[2 * q + 1], lo[2 * q + 1]);
        }
        char* ph = scr + row * 144 + half * 64;
        char* pl = ph + 2304;
#pragma unroll
        for (int q = 0; q < 4; q++) {
            *(uint4*)(ph + q * 16) = make_uint4(hi[4 * q], hi[4 * q + 1], hi[4 * q + 2], hi[4 * q + 3]);
            *(uint4*)(pl + q * 16) = make_uint4(lo[4 * q], lo[4 * q + 1], lo[4 * q + 2], lo[4 * q + 3]);
        }
    }
    __syncwarp();

    for (; wt < numWT; wt += stride) {
        const int base = wt * 16;
        const int nwt = wt + stride;

        // capture this tile's indices before strip is restaged
        const int s0 = strip[gid],     d0 = strip[16 + gid];
        const int s1 = strip[gid + 8], d1 = strip[24 + gid];
        const int mydst = strip[L];

        u32 aH[4][4], aL[4][4];
#pragma unroll
        for (int ks = 0; ks < 4; ks++) {
            ldmx4(SCRw + a_lane144 + ks * 32,        aH[ks][0], aH[ks][1], aH[ks][2], aH[ks][3]);
            ldmx4(SCRw + 2304 + a_lane144 + ks * 32, aL[ks][0], aL[ks][1], aL[ks][2], aL[ks][3]);
        }
        __syncwarp();   // A1 scratch free (A2 overwrites it)

        // ---- L1 ----
#pragma unroll
        for (int nt = 0; nt < 16; nt++) {
            u32 bh[8], bl[8];
            u32 wbH = smb + SB_W1H + (u32)nt * 8 * 144 + b_lane144;
            u32 wbL = smb + SB_W1L + (u32)nt * 8 * 144 + b_lane144;
            ldmx4(wbH,      bh[0], bh[1], bh[2], bh[3]);
            ldmx4(wbH + 64, bh[4], bh[5], bh[6], bh[7]);
            ldmx4(wbL,      bl[0], bl[1], bl[2], bl[3]);
            ldmx4(wbL + 64, bl[4], bl[5], bl[6], bl[7]);
            float c[4] = {0.f, 0.f, 0.f, 0.f};
#pragma unroll
            for (int ks = 0; ks < 4; ks++) {
                mma16816(c, aH[ks], bh[2 * ks], bh[2 * ks + 1]);
                mma16816(c, aL[ks], bh[2 * ks], bh[2 * ks + 1]);
                mma16816(c, aH[ks], bl[2 * ks], bl[2 * ks + 1]);
            }
            int col = 8 * nt + 2 * tig;
            float2 bb = *(float2*)(sB1f + col);
            float2 pa0 = *(const float2*)(g_pre_a + (size_t)s0 * 128 + col);
            float2 pb0 = *(const float2*)(g_pre_b + (size_t)d0 * 128 + col);
            float2 pa1 = *(const float2*)(g_pre_a + (size_t)s1 * 128 + col);
            float2 pb1v = *(const float2*)(g_pre_b + (size_t)d1 * 128 + col);
            float v00 = sspf(c[0] + pa0.x + pb0.x + bb.x);
            float v01 = sspf(c[1] + pa0.y + pb0.y + bb.y);
            float v10 = sspf(c[2] + pa1.x + pb1v.x + bb.x);
            float v11 = sspf(c[3] + pa1.y + pb1v.y + bb.y);
            u32 h0, l0, h1, l1;
            split2(v00, v01, h0, l0);
            split2(v10, v11, h1, l1);
            u32 o0 = (u32)gid * 272 + (u32)col * 2;
            u32 o1 = (u32)(gid + 8) * 272 + (u32)col * 2;
            *(u32*)(scr + o0) = h0;
            *(u32*)(scr + 4352 + o0) = l0;
            *(u32*)(scr + o1) = h1;
            *(u32*)(scr + 4352 + o1) = l1;
        }
        __syncwarp();

        u32 a2H[8][4], a2L[8][4];
#pragma unroll
        for (int ks = 0; ks < 8; ks++) {
            ldmx4(SCRw + a_lane272 + ks * 32,        a2H[ks][0], a2H[ks][1], a2H[ks][2], a2H[ks][3]);
            ldmx4(SCRw + 4352 + a_lane272 + ks * 32, a2L[ks][0], a2L[ks][1], a2L[ks][2], a2L[ks][3]);
        }
        __syncwarp();

        // ---- L2 ----
#pragma unroll
        for (int nt = 0; nt < 8; nt++) {
            u32 bh[16], bl[16];
            u32 wbH = smb + SB_W2H + (u32)nt * 8 * 272 + b_lane272;
            u32 wbL = smb + SB_W2L + (u32)nt * 8 * 272 + b_lane272;
#pragma unroll
            for (int kp = 0; kp < 4; kp++) {
                ldmx4(wbH + kp * 64, bh[4 * kp], bh[4 * kp + 1], bh[4 * kp + 2], bh[4 * kp + 3]);
                ldmx4(wbL + kp * 64, bl[4 * kp], bl[4 * kp + 1], bl[4 * kp + 2], bl[4 * kp + 3]);
            }
            float c[4] = {0.f, 0.f, 0.f, 0.f};
#pragma unroll
            for (int ks = 0; ks < 8; ks++) {
                mma16816(c, a2H[ks], bh[2 * ks], bh[2 * ks + 1]);
                mma16816(c, a2L[ks], bh[2 * ks], bh[2 * ks + 1]);
                mma16816(c, a2H[ks], bl[2 * ks], bl[2 * ks + 1]);
            }
            int col = 8 * nt + 2 * tig;
            float2 bb = *(float2*)(sB2f + col);
            float v00 = c[0] + bb.x, v01 = c[1] + bb.y;
            float v10 = c[2] + bb.x, v11 = c[3] + bb.y;
            if (base + gid < E)
                *(float2*)(out_edge + (size_t)(base + gid) * 64 + col) = make_float2(v00, v01);
            if (base + gid + 8 < E)
                *(float2*)(out_edge + (size_t)(base + gid + 8) * 64 + col) = make_float2(v10, v11);
            u32 h0, l0, h1, l1;
            split2(v00, v01, h0, l0);
            split2(v10, v11, h1, l1);
            u32 o0 = (u32)gid * 144 + (u32)col * 2;
            u32 o1 = (u32)(gid + 8) * 144 + (u32)col * 2;
            *(u32*)(scr + o0) = h0;
            *(u32*)(scr + 2304 + o0) = l0;
            *(u32*)(scr + o1) = h1;
            *(u32*)(scr + 2304 + o1) = l1;
        }
        __syncwarp();

        u32 a3H[4][4], a3L[4][4];
#pragma unroll
        for (int ks = 0; ks < 4; ks++) {
            ldmx4(SCRw + a_lane144 + ks * 32,        a3H[ks][0], a3H[ks][1], a3H[ks][2], a3H[ks][3]);
            ldmx4(SCRw + 2304 + a_lane144 + ks * 32, a3L[ks][0], a3L[ks][1], a3L[ks][2], a3L[ks][3]);
        }
        __syncwarp();   // A3 frags in regs -> scratch fully free

        // ---- stage NEXT tile (LDG latency hides behind L3 mma burst) ----
        {
            int v = 0;
            int nb = nwt * 16;
            if (L < 16) { int g = nb + L;      if (nwt < numWT && g < E) v = srcp[g]; }
            else        { int g = nb + L - 16; if (nwt < numWT && g < E) v = dstp[g]; }
            strip[L] = v;
            bool ok = (nwt < numWT) && (nb + row) < E;
            const float4* gp = (const float4*)(edge_feats + (size_t)(nb + row) * 64 + half * 32);
            u32 hi[16], lo[16];
#pragma unroll
            for (int q = 0; q < 8; q++) {
                float4 v4 = ok ? gp[q] : make_float4(0.f, 0.f, 0.f, 0.f);
                split2(v4.x, v4.y, hi[2 * q], lo[2 * q]);
                split2(v4.z, v4.w, hi[2 * q + 1], lo[2 * q + 1]);
            }
            char* ph = scr + row * 144 + half * 64;
            char* pl = ph + 2304;
#pragma unroll
            for (int q = 0; q < 4; q++) {
                *(uint4*)(ph + q * 16) = make_uint4(hi[4 * q], hi[4 * q + 1], hi[4 * q + 2], hi[4 * q + 3]);
                *(uint4*)(pl + q * 16) = make_uint4(lo[4 * q], lo[4 * q + 1], lo[4 * q + 2], lo[4 * q + 3]);
            }
        }

        // ---- L3 ----
#pragma unroll
        for (int nt = 0; nt < 8; nt++) {
            u32 bh[8], bl[8];
            u32 wbH = smb + SB_P1H + (u32)nt * 8 * 144 + b_lane144;
            u32 wbL = smb + SB_P1L + (u32)nt * 8 * 144 + b_lane144;
            ldmx4(wbH,      bh[0], bh[1], bh[2], bh[3]);
            ldmx4(wbH + 64, bh[4], bh[5], bh[6], bh[7]);
            ldmx4(wbL,      bl[0], bl[1], bl[2], bl[3]);
            ldmx4(wbL + 64, bl[4], bl[5], bl[6], bl[7]);
            float c[4] = {0.f, 0.f, 0.f, 0.f};
#pragma unroll
            for (int ks = 0; ks < 4; ks++) {
                mma16816(c, a3H[ks], bh[2 * ks], bh[2 * ks + 1]);
                mma16816(c, a3L[ks], bh[2 * ks], bh[2 * ks + 1]);
                mma16816(c, a3H[ks], bl[2 * ks], bl[2 * ks + 1]);
            }
            int col = 8 * nt + 2 * tig;
            float2 bb = *(float2*)(sPb1f + col);
            if (base + gid < E)
                red_v2(agg + (size_t)d0 * 64 + col,
                       sspf(c[0] + bb.x), sspf(c[1] + bb.y));
            if (base + gid + 8 < E)
                red_v2(agg + (size_t)d1 * 64 + col,
                       sspf(c[2] + bb.x), sspf(c[3] + bb.y));
        }
        if (L >= 16 && base + (L - 16) < E) atomicAdd(g_deg + mydst, 1.0f);
        __syncwarp();
    }
}

// ---------------- node precompute: HMMA bf16 3-term, 16-node warp tiles ----
#define NP_W1AH 0        // [128 j][144B] 18432
#define NP_W1AL 18432
#define NP_W1BH 36864
#define NP_W1BL 55296
#define NP_SCRB 73728    // 12 x 4608
#define NPRE_SMEM 129024

__global__ void __launch_bounds__(TPB, 1)
node_pre_kernel(const float* __restrict__ node_feats,
                const float* __restrict__ eu_w1, int N, int numNT) {
    extern __shared__ char smem[];
    const int tid = threadIdx.x;
    const int w = tid >> 5, L = tid & 31;
    const int gid = L >> 2, tig = L & 3;

    for (int i = tid; i < 128 * 64; i += TPB) {
        int j = i >> 6, k = i & 63;
        float wa = eu_w1[k * 128 + j];
        float wb = eu_w1[(64 + k) * 128 + j];
        __nv_bfloat16 ha = __float2bfloat16(wa);
        __nv_bfloat16 hb = __float2bfloat16(wb);
        float la = wa - __bfloat162float(ha);
        float lb = wb - __bfloat162float(hb);
        *(__nv_bfloat16*)(smem + NP_W1AH + j * 144 + k * 2) = ha;
        *(__nv_bfloat16*)(smem + NP_W1AL + j * 144 + k * 2) = __float2bfloat16(la);
        *(__nv_bfloat16*)(smem + NP_W1BH + j * 144 + k * 2) = hb;
        *(__nv_bfloat16*)(smem + NP_W1BL + j * 144 + k * 2) = __float2bfloat16(lb);
    }
    __syncthreads();

    const u32 smb = smem_u32(smem);
    char* scr = smem + NP_SCRB + w * 4608;
    const u32 SCRw = smb + NP_SCRB + (u32)w * 4608;
    const u32 a_lane144 = (u32)(L & 15) * 144 + ((u32)(L >> 4) << 4);
    const u32 b_lane144 = (u32)(L & 7) * 144 + ((u32)(L >> 3) << 4);

    for (int nt_tile = blockIdx.x * NW + w; nt_tile < numNT; nt_tile += gridDim.x * NW) {
        const int base = nt_tile * 16;
        {
            int row = L >> 1, half = L & 1;
            bool ok = (base + row) < N;
            const float4* gp = (const float4*)(node_feats + (size_t)(base + row) * 64 + half * 32);
            u32 hi[16], lo[16];
#pragma unroll
            for (int q = 0; q < 8; q++) {
                float4 v4 = ok ? gp[q] : make_float4(0.f, 0.f, 0.f, 0.f);
                split2(v4.x, v4.y, hi[2 * q], lo[2 * q]);
                split2(v4.z, v4.w, hi[2 * q + 1], lo[2 * q + 1]);
            }
            char* ph = scr + row * 144 + half * 64;
            char* pl = ph + 2304;
#pragma unroll
            for (int q = 0; q < 4; q++) {
                *(uint4*)(ph + q * 16) = make_uint4(hi[4 * q], hi[4 * q + 1], hi[4 * q + 2], hi[4 * q + 3]);
                *(uint4*)(pl + q * 16) = make_uint4(lo[4 * q], lo[4 * q + 1], lo[4 * q + 2], lo[4 * q + 3]);
            }
        }
        __syncwarp();

        u32 aH[4][4], aL[4][4];
#pragma unroll
        for (int ks = 0; ks < 4; ks++) {
            ldmx4(SCRw + a_lane144 + ks * 32,        aH[ks][0], aH[ks][1], aH[ks][2], aH[ks][3]);
            ldmx4(SCRw + 2304 + a_lane144 + ks * 32, aL[ks][0], aL[ks][1], aL[ks][2], aL[ks][3]);
        }

        const bool ok0 = (base + gid) < N, ok1 = (base + gid + 8) < N;
        float* outs[2] = { g_pre_a, g_pre_b };
        const u32 wbase[2] = { NP_W1AH, NP_W1BH };
#pragma unroll
        for (int half = 0; half < 2; half++) {
            float* outp = outs[half];
#pragma unroll
            for (int nt = 0; nt < 16; nt++) {
                u32 bh[8], bl[8];
                u32 wbH = smb + wbase[half] + (u32)nt * 8 * 144 + b_lane144;
                u32 wbL = wbH + 18432;
                ldmx4(wbH,      bh[0], bh[1], bh[2], bh[3]);
                ldmx4(wbH + 64, bh[4], bh[5], bh[6], bh[7]);
                ldmx4(wbL,      bl[0], bl[1], bl[2], bl[3]);
                ldmx4(wbL + 64, bl[4], bl[5], bl[6], bl[7]);
                float c[4] = {0.f, 0.f, 0.f, 0.f};
#pragma unroll
                for (int ks = 0; ks < 4; ks++) {
                    mma16816(c, aH[ks], bh[2 * ks], bh[2 * ks + 1]);
                    mma16816(c, aL[ks], bh[2 * ks], bh[2 * ks + 1]);
                    mma16816(c, aH[ks], bl[2 * ks], bl[2 * ks + 1]);
                }
                int col = 8 * nt + 2 * tig;
                if (ok0)
                    *(float2*)(outp + (size_t)(base + gid) * 128 + col) = make_float2(c[0], c[1]);
                if (ok1)
                    *(float2*)(outp + (size_t)(base + gid + 8) * 128 + col) = make_float2(c[2], c[3]);
            }
        }
        __syncwarp();
    }
}

// ---------------- node post: HMMA bf16 3-term, 16-node warp tiles ----------
#define NPO_P2H 0        // [64 j][144B] 9216
#define NPO_P2L 9216
#define NPO_W1H 18432
#define NPO_W1L 27648
#define NPO_W2H 36864
#define NPO_W2L 46080
#define NPO_PB2 55296    // 64 f32
#define NPO_B1  55552
#define NPO_B2  55808
#define NPO_SCR 56064    // 12 x 4608
#define NPO_SMEM 111360

__global__ void __launch_bounds__(TPB, 1)
node_post_kernel(const float* __restrict__ node_feats,
                 const float* __restrict__ pe_w2, const float* __restrict__ pe_b2,
                 const float* __restrict__ w1, const float* __restrict__ b1,
                 const float* __restrict__ w2, const float* __restrict__ b2,
                 float* __restrict__ node_out, int N, int numNT) {
    extern __shared__ char smem[];
    float* sPb2 = (float*)(smem + NPO_PB2);
    float* sB1f = (float*)(smem + NPO_B1);
    float* sB2f = (float*)(smem + NPO_B2);
    const int tid = threadIdx.x;
    const int w = tid >> 5, L = tid & 31;
    const int gid = L >> 2, tig = L & 3;

    for (int i = tid; i < 64 * 64; i += TPB) {
        int k = i >> 6, j = i & 63;
        float wv = pe_w2[i];
        __nv_bfloat16 h = __float2bfloat16(wv);
        *(__nv_bfloat16*)(smem + NPO_P2H + j * 144 + k * 2) = h;
        *(__nv_bfloat16*)(smem + NPO_P2L + j * 144 + k * 2) = __float2bfloat16(wv - __bfloat162float(h));
        wv = w1[i];
        h = __float2bfloat16(wv);
        *(__nv_bfloat16*)(smem + NPO_W1H + j * 144 + k * 2) = h;
        *(__nv_bfloat16*)(smem + NPO_W1L + j * 144 + k * 2) = __float2bfloat16(wv - __bfloat162float(h));
        wv = w2[i];
        h = __float2bfloat16(wv);
        *(__nv_bfloat16*)(smem + NPO_W2H + j * 144 + k * 2) = h;
        *(__nv_bfloat16*)(smem + NPO_W2L + j * 144 + k * 2) = __float2bfloat16(wv - __bfloat162float(h));
    }
    if (tid < 64) { sPb2[tid] = pe_b2[tid]; sB1f[tid] = b1[tid]; sB2f[tid] = b2[tid]; }
    __syncthreads();

    const u32 smb = smem_u32(smem);
    char* scr = smem + NPO_SCR + w * 4608;
    const u32 SCRw = smb + NPO_SCR + (u32)w * 4608;
    const u32 a_lane144 = (u32)(L & 15) * 144 + ((u32)(L >> 4) << 4);
    const u32 b_lane144 = (u32)(L & 7) * 144 + ((u32)(L >> 3) << 4);

    for (int t = blockIdx.x * NW + w; t < numNT; t += gridDim.x * NW) {
        const int base = t * 16;
        {
            int row = L >> 1, hf = L & 1;
            bool ok = (base + row) < N;
            const float4* gp = (const float4*)(node_out + (size_t)(base + row) * 64 + hf * 32);
            u32 hi[16], lo[16];
#pragma unroll
            for (int q = 0; q < 8; q++) {
                float4 v4 = ok ? gp[q] : make_float4(0.f, 0.f, 0.f, 0.f);
                split2(v4.x, v4.y, hi[2 * q], lo[2 * q]);
                split2(v4.z, v4.w, hi[2 * q + 1], lo[2 * q + 1]);
            }
            char* ph = scr + row * 144 + hf * 64;
            char* pl = ph + 2304;
#pragma unroll
            for (int q = 0; q < 4; q++) {
                *(uint4*)(ph + q * 16) = make_uint4(hi[4 * q], hi[4 * q + 1], hi[4 * q + 2], hi[4 * q + 3]);
                *(uint4*)(pl + q * 16) = make_uint4(lo[4 * q], lo[4 * q + 1], lo[4 * q + 2], lo[4 * q + 3]);
            }
        }
        __syncwarp();
        u32 aH[4][4], aL[4][4];
#pragma unroll
        for (int ks = 0; ks < 4; ks++) {
            ldmx4(SCRw + a_lane144 + ks * 32,        aH[ks][0], aH[ks][1], aH[ks][2], aH[ks][3]);
            ldmx4(SCRw + 2304 + a_lane144 + ks * 32, aL[ks][0], aL[ks][1], aL[ks][2], aL[ks][3]);
        }
        __syncwarp();

        const bool ok0 = (base + gid) < N, ok1 = (base + gid + 8) < N;
        float dg0 = ok0 ? g_deg[base + gid] : 0.0f;
        float dg1 = ok1 ? g_deg[base + gid + 8] : 0.0f;

        // ---- P1: X = A @ pe_w2 + deg*pb2 -> scratch ----
#pragma unroll
        for (int nt = 0; nt < 8; nt++) {
            u32 bh[8], bl[8];
            u32 wbH = smb + NPO_P2H + (u32)nt * 8 * 144 + b_lane144;
            u32 wbL = smb + NPO_P2L + (u32)nt * 8 * 144 + b_lane144;
            ldmx4(wbH,      bh[0], bh[1], bh[2], bh[3]);
            ldmx4(wbH + 64, bh[4], bh[5], bh[6], bh[7]);
            ldmx4(wbL,      bl[0], bl[1], bl[2], bl[3]);
            ldmx4(wbL + 64, bl[4], bl[5], bl[6], bl[7]);
            float c[4] = {0.f, 0.f, 0.f, 0.f};
#pragma unroll
            for (int ks = 0; ks < 4; ks++) {
                mma16816(c, aH[ks], bh[2 * ks], bh[2 * ks + 1]);
                mma16816(c, aL[ks], bh[2 * ks], bh[2 * ks + 1]);
                mma16816(c, aH[ks], bl[2 * ks], bl[2 * ks + 1]);
            }
            int col = 8 * nt + 2 * tig;
            float2 bb = *(float2*)(sPb2 + col);
            float x00 = c[0] + dg0 * bb.x, x01 = c[1] + dg0 * bb.y;
            float x10 = c[2] + dg1 * bb.x, x11 = c[3] + dg1 * bb.y;
            u32 h0, l0, h1, l1;
            split2(x00, x01, h0, l0);
            split2(x10, x11, h1, l1);
            u32 o0 = (u32)gid * 144 + (u32)col * 2;
            u32 o1 = (u32)(gid + 8) * 144 + (u32)col * 2;
            *(u32*)(scr + o0) = h0;
            *(u32*)(scr + 2304 + o0) = l0;
            *(u32*)(scr + o1) = h1;
            *(u32*)(scr + 2304 + o1) = l1;
        }
        __syncwarp();
        u32 xH[4][4], xL[4][4];
#pragma unroll
        for (int ks = 0; ks < 4; ks++) {
            ldmx4(SCRw + a_lane144 + ks * 32,        xH[ks][0], xH[ks][1], xH[ks][2], xH[ks][3]);
            ldmx4(SCRw + 2304 + a_lane144 + ks * 32, xL[ks][0], xL[ks][1], xL[ks][2], xL[ks][3]);
        }
        __syncwarp();

        // ---- P2: T = ssp(X @ w1 + b1) -> scratch ----
#pragma unroll
        for (int nt = 0; nt < 8; nt++) {
            u32 bh[8], bl[8];
            u32 wbH = smb + NPO_W1H + (u32)nt * 8 * 144 + b_lane144;
            u32 wbL = smb + NPO_W1L + (u32)nt * 8 * 144 + b_lane144;
            ldmx4(wbH,      bh[0], bh[1], bh[2], bh[3]);
            ldmx4(wbH + 64, bh[4], bh[5], bh[6], bh[7]);
            ldmx4(wbL,      bl[0], bl[1], bl[2], bl[3]);
            ldmx4(wbL + 64, bl[4], bl[5], bl[6], bl[7]);
            float c[4] = {0.f, 0.f, 0.f, 0.f};
#pragma unroll
            for (int ks = 0; ks < 4; ks++) {
                mma16816(c, xH[ks], bh[2 * ks], bh[2 * ks + 1]);
                mma16816(c, xL[ks], bh[2 * ks], bh[2 * ks + 1]);
                mma16816(c, xH[ks], bl[2 * ks], bl[2 * ks + 1]);
            }
            int col = 8 * nt + 2 * tig;
            float2 bb = *(float2*)(sB1f + col);
            float t00 = sspf(c[0] + bb.x), t01 = sspf(c[1] + bb.y);
            float t10 = sspf(c[2] + bb.x), t11 = sspf(c[3] + bb.y);
            u32 h0, l0, h1, l1;
            split2(t00, t01, h0, l0);
            split2(t10, t11, h1, l1);
            u32 o0 = (u32)gid * 144 + (u32)col * 2;
            u32 o1 = (u32)(gid + 8) * 144 + (u32)col * 2;
            *(u32*)(scr + o0) = h0;
            *(u32*)(scr + 2304 + o0) = l0;
            *(u32*)(scr + o1) = h1;
            *(u32*)(scr + 2304 + o1) = l1;
        }
        __syncwarp();
        u32 tH[4][4], tL[4][4];
#pragma unroll
        for (int ks = 0; ks < 4; ks++) {
            ldmx4(SCRw + a_lane144 + ks * 32,        tH[ks][0], tH[ks][1], tH[ks][2], tH[ks][3]);
            ldmx4(SCRw + 2304 + a_lane144 + ks * 32, tL[ks][0], tL[ks][1], tL[ks][2], tL[ks][3]);
        }

        // ---- P3: out = nf + T @ w2 + b2 ----
#pragma unroll
        for (int nt = 0; nt < 8; nt++) {
            u32 bh[8], bl[8];
            u32 wbH = smb + NPO_W2H + (u32)nt * 8 * 144 + b_lane144;
            u32 wbL = smb + NPO_W2L + (u32)nt * 8 * 144 + b_lane144;
            ldmx4(wbH,      bh[0], bh[1], bh[2], bh[3]);
            ldmx4(wbH + 64, bh[4], bh[5], bh[6], bh[7]);
            ldmx4(wbL,      bl[0], bl[1], bl[2], bl[3]);
            ldmx4(wbL + 64, bl[4], bl[5], bl[6], bl[7]);
            float c[4] = {0.f, 0.f, 0.f, 0.f};
#pragma unroll
            for (int ks = 0; ks < 4; ks++) {
                mma16816(c, tH[ks], bh[2 * ks], bh[2 * ks + 1]);
                mma16816(c, tL[ks], bh[2 * ks], bh[2 * ks + 1]);
                mma16816(c, tH[ks], bl[2 * ks], bl[2 * ks + 1]);
            }
            int col = 8 * nt + 2 * tig;
            float2 bb = *(float2*)(sB2f + col);
            if (ok0) {
                float2 nf = *(const float2*)(node_feats + (size_t)(base + gid) * 64 + col);
                *(float2*)(node_out + (size_t)(base + gid) * 64 + col) =
                    make_float2(c[0] + bb.x + nf.x, c[1] + bb.y + nf.y);
            }
            if (ok1) {
                float2 nf = *(const float2*)(node_feats + (size_t)(base + gid + 8) * 64 + col);
                *(float2*)(node_out + (size_t)(base + gid + 8) * 64 + col) =
                    make_float2(c[2] + bb.x + nf.x, c[3] + bb.y + nf.y);
            }
        }
        __syncwarp();
    }
}

extern "C" void kernel_launch(void* const* d_in, const int* in_sizes, int n_in,
                              void* d_out, int out_size) {
    const float* node_feats = (const float*)d_in[0];
    const float* edge_feats = (const float*)d_in[1];
    const int*   src  = (const int*)d_in[2];
    const int*   dst  = (const int*)d_in[3];
    const float* eu_w1 = (const float*)d_in[4];
    const float* eu_b1 = (const float*)d_in[5];
    const float* eu_w2 = (const float*)d_in[6];
    const float* eu_b2 = (const float*)d_in[7];
    const float* pe_w1 = (const float*)d_in[10];
    const float* pe_b1 = (const float*)d_in[11];
    const float* pe_w2 = (const float*)d_in[12];
    const float* pe_b2 = (const float*)d_in[13];
    const float* pn2_w1 = (const float*)d_in[14];
    const float* pn2_b1 = (const float*)d_in[15];
    const float* pn2_w2 = (const float*)d_in[16];
    const float* pn2_b2 = (const float*)d_in[17];

    const int N = in_sizes[0] / 64;
    const int E = in_sizes[1] / 64;
    float* out_node = (float*)d_out;
    float* out_edge = out_node + (size_t)N * 64;

    cudaFuncSetAttribute(edge_kernel, cudaFuncAttributeMaxDynamicSharedMemorySize, SMEM_BYTES);
    cudaFuncSetAttribute(node_pre_kernel, cudaFuncAttributeMaxDynamicSharedMemorySize, NPRE_SMEM);
    cudaFuncSetAttribute(node_post_kernel, cudaFuncAttributeMaxDynamicSharedMemorySize, NPO_SMEM);

    cudaMemsetAsync(out_node, 0, (size_t)N * 64 * sizeof(float));
    void* degp = 0;
    cudaGetSymbolAddress(&degp, g_deg);
    cudaMemsetAsync(degp, 0, (size_t)N * sizeof(float));

    int sms = 0;
    cudaDeviceGetAttribute(&sms, cudaDevAttrMultiProcessorCount, 0);
    if (sms <= 0) sms = 148;

    int numNT = (N + 15) / 16;
    int gpre = sms;
    if (gpre * NW > numNT) gpre = (numNT + NW - 1) / NW;
    if (gpre < 1) gpre = 1;
    node_pre_kernel<<<gpre, TPB, NPRE_SMEM>>>(node_feats, eu_w1, N, numNT);

    int numWT = (E + 15) / 16;
    int grid = sms;
    if (grid * NW > numWT) grid = (numWT + NW - 1) / NW;
    if (grid < 1) grid = 1;
    edge_kernel<<<grid, TPB, SMEM_BYTES>>>(
        edge_feats, src, dst, eu_w1, eu_b1, eu_w2, eu_b2,
        pe_w1, pe_b1, out_node, out_edge, E, numWT);

    node_post_kernel<<<gpre, TPB, NPO_SMEM>>>(
        node_feats, pe_w2, pe_b2, pn2_w1, pn2_b1, pn2_w2, pn2_b2,
        out_node, N, numNT);
}